// round 12
// baseline (speedup 1.0000x reference)
#include <cuda_runtime.h>
#include <cuda_bf16.h>
#include <math.h>

#define BB 512
#define TT 64
#define NINx 63
#define HH 128

typedef unsigned long long ull_t;

// ------------------------- device scratch (static) -------------------------
__device__ float g_attn[BB * 64];
__device__ float g_gin[(size_t)BB * TT * 512];    // permuted gate order, biases folded
__device__ float g_enc[(size_t)BB * TT * HH];     // input_encoded [b][t][e] fp32
__device__ float g_eproj[(size_t)BB * TT * HH];   // enc_proj (+dec_b1) fp32
__device__ unsigned int g_WhhB[2][128 * 256];     // [enc/dec][k][g/2] bf16x2, permuted
__device__ unsigned int g_W1hcB[128 * 128];       // [k2][e] bf16x2 of (W1h;W1c)^T pairs
__device__ float g_dWihP[512], g_dbP[512];        // permuted dec input weights/biases

__device__ __forceinline__ float tanh_fast(float v) {
    float r; asm("tanh.approx.f32 %0, %1;" : "=f"(r) : "f"(v)); return r;
}
__device__ __forceinline__ float sig_fast(float v) {
    return 0.5f * tanh_fast(0.5f * v) + 0.5f;
}
__device__ __forceinline__ unsigned int pack_bf16x2(float a, float b) {
    __nv_bfloat162 p = __floats2bfloat162_rn(a, b);
    return *reinterpret_cast<unsigned int*>(&p);
}
__device__ __forceinline__ float2 unpack_bf16x2(unsigned int u) {
    return __bfloat1622float2(*reinterpret_cast<__nv_bfloat162*>(&u));
}
// ---- packed f32x2 helpers (Blackwell) ----
__device__ __forceinline__ ull_t pack2(float lo, float hi) {
    ull_t r; asm("mov.b64 %0, {%1, %2};" : "=l"(r) : "f"(lo), "f"(hi)); return r;
}
__device__ __forceinline__ float2 unpk(ull_t v) {
    float2 f; asm("mov.b64 {%0, %1}, %2;" : "=f"(f.x), "=f"(f.y) : "l"(v)); return f;
}
__device__ __forceinline__ void fma2(ull_t& d, ull_t a, ull_t b) {
    asm("fma.rn.f32x2 %0, %1, %2, %0;" : "+l"(d) : "l"(a), "l"(b));
}
__device__ __forceinline__ float bf_lo(unsigned int u) { return __uint_as_float(u << 16); }
__device__ __forceinline__ float bf_hi(unsigned int u) { return __uint_as_float(u & 0xFFFF0000u); }

#define BAR_ATTN() asm volatile("bar.sync 1, 256;" ::: "memory")
#define BAR_GATE() asm volatile("bar.sync 2, 256;" ::: "memory")

// ------------------------- weight prep (permute + transpose + bf16) -------------------------
__global__ void prep_weights(const float* __restrict__ eWhh,
                             const float* __restrict__ dWhh,
                             const float* __restrict__ dWih,
                             const float* __restrict__ dbih,
                             const float* __restrict__ dbhh,
                             const float* __restrict__ dW1) {
    int i = blockIdx.x * 256 + threadIdx.x;
    if (i < 32768) {
        int k = i >> 8, g2 = i & 255;
        int gp0 = 2 * g2, gp1 = 2 * g2 + 1;
        int o0 = (gp0 & 3) * HH + (gp0 >> 2);
        int o1 = (gp1 & 3) * HH + (gp1 >> 2);
        g_WhhB[0][k * 256 + g2] = pack_bf16x2(eWhh[o0 * HH + k], eWhh[o1 * HH + k]);
        g_WhhB[1][k * 256 + g2] = pack_bf16x2(dWhh[o0 * HH + k], dWhh[o1 * HH + k]);
    } else if (i < 33280) {
        int gp = i - 32768;
        int orig = (gp & 3) * HH + (gp >> 2);
        g_dWihP[gp] = dWih[orig];
        g_dbP[gp] = dbih[orig] + dbhh[orig];
    } else if (i < 33280 + 16384) {
        int j = i - 33280;
        int e = j & 127, k2 = j >> 7;   // k2 0..127 covers k 0..255 (W1h then W1c)
        g_W1hcB[k2 * 128 + e] = pack_bf16x2(dW1[e * 384 + 2 * k2],
                                            dW1[e * 384 + 2 * k2 + 1]);
    }
}

// ------------------------- encoder attention (time- & state-invariant) -------------------------
__global__ void prep_attn(const float* __restrict__ x,
                          const float* __restrict__ attnW,
                          const float* __restrict__ attnB) {
    __shared__ float s_s[64];
    __shared__ float red[2];
    int b = blockIdx.x, n = threadIdx.x;
    float s = -1e30f;
    if (n < NINx) {
        float acc = attnB[0];
        const float* wt = attnW + 2 * HH;
        #pragma unroll 8
        for (int t = 0; t < TT; t++) acc = fmaf(x[b * 4096 + t * 64 + n + 1], wt[t], acc);
        s = acc;
    }
    s_s[n] = s;
    __syncthreads();
    if (n < 32) {
        float m = fmaxf(s_s[n], s_s[n + 32]);
        #pragma unroll
        for (int o = 16; o; o >>= 1) m = fmaxf(m, __shfl_xor_sync(0xffffffffu, m, o));
        if (n == 0) red[0] = m;
    }
    __syncthreads();
    float e = (n < NINx) ? expf(s - red[0]) : 0.f;
    s_s[n] = e;
    __syncthreads();
    if (n < 32) {
        float sm = s_s[n] + s_s[n + 32];
        #pragma unroll
        for (int o = 16; o; o >>= 1) sm += __shfl_xor_sync(0xffffffffu, sm, o);
        if (n == 0) red[1] = sm;
    }
    __syncthreads();
    if (n < 64) g_attn[b * 64 + n] = (n < NINx) ? e / red[1] : 0.f;
}

// ------------- gin[b,t,g'] = sum_n attn[b,n]*x[b,t,n+1]*Wih[orig(g'),n] + bias -------------
__global__ __launch_bounds__(256) void gin_gemm(const float* __restrict__ x,
                                                const float* __restrict__ Wih,
                                                const float* __restrict__ bih,
                                                const float* __restrict__ bhh) {
    __shared__ float attn_s[64];
    __shared__ float As[64][68];
    __shared__ float Ws[64][68];
    int bb = blockIdx.x;
    int g0 = blockIdx.y * 64;
    int tid = threadIdx.x;
    if (tid < 64) attn_s[tid] = g_attn[bb * 64 + tid];
    __syncthreads();
    #pragma unroll
    for (int i = 0; i < 16; i++) {
        int idx = tid + i * 256;
        int m = idx >> 6, k = idx & 63;
        As[k][m] = (k < NINx) ? attn_s[k] * x[bb * 4096 + m * 64 + k + 1] : 0.f;
        int gp = g0 + m;
        int orig = (gp & 3) * HH + (gp >> 2);
        Ws[k][m] = (k < NINx) ? Wih[orig * NINx + k] : 0.f;
    }
    __syncthreads();
    int tx = tid & 15, ty = tid >> 4;
    float acc[4][4];
    #pragma unroll
    for (int i = 0; i < 4; i++)
        #pragma unroll
        for (int j = 0; j < 4; j++) acc[i][j] = 0.f;
    #pragma unroll 4
    for (int k = 0; k < 64; k++) {
        float4 a = *reinterpret_cast<const float4*>(&As[k][ty * 4]);
        float4 w = *reinterpret_cast<const float4*>(&Ws[k][tx * 4]);
        float av[4] = {a.x, a.y, a.z, a.w};
        float wv[4] = {w.x, w.y, w.z, w.w};
        #pragma unroll
        for (int i = 0; i < 4; i++)
            #pragma unroll
            for (int j = 0; j < 4; j++) acc[i][j] = fmaf(av[i], wv[j], acc[i][j]);
    }
    #pragma unroll
    for (int i = 0; i < 4; i++) {
        int t = ty * 4 + i;
        #pragma unroll
        for (int j = 0; j < 4; j++) {
            int gp = g0 + tx * 4 + j;
            int orig = (gp & 3) * HH + (gp >> 2);
            g_gin[((size_t)bb * TT + t) * 512 + gp] = acc[i][j] + bih[orig] + bhh[orig];
        }
    }
}

// ------------------------- persistent encoder: 128 blocks x 4 batches, 64 steps -------------------------
struct EncSmem {
    unsigned int whh[128][256];   // bf16x2 [k][g/2]   128 KB
    float hT[128][4];             // [unit][batch]
    float part[3][16][128];       // partials from kq=1..3
};

__global__ __launch_bounds__(512) void enc_persist() {
    extern __shared__ __align__(16) char enc_smem_raw[];
    EncSmem& S = *reinterpret_cast<EncSmem*>(enc_smem_raw);
    int b0 = blockIdx.x * 4;
    int tid = threadIdx.x;
    int ug = tid & 127, kq = tid >> 7;
    {
        const uint4* src = reinterpret_cast<const uint4*>(g_WhhB[0]);
        uint4* dst = reinterpret_cast<uint4*>(&S.whh[0][0]);
        for (int i = tid; i < 8192; i += 512) dst[i] = src[i];
    }
    if (tid < 128) *reinterpret_cast<float4*>(S.hT[tid]) = make_float4(0.f, 0.f, 0.f, 0.f);
    float c0 = 0.f, c1 = 0.f, c2 = 0.f, c3 = 0.f;
    __syncthreads();
    for (int t = 0; t < 64; t++) {
        float4 gin0, gin1, gin2, gin3;
        if (kq == 0) {
            const float* gp = g_gin + ((size_t)b0 * 64 + t) * 512 + ug * 4;
            gin0 = *reinterpret_cast<const float4*>(gp);
            gin1 = *reinterpret_cast<const float4*>(gp + 32768);
            gin2 = *reinterpret_cast<const float4*>(gp + 65536);
            gin3 = *reinterpret_cast<const float4*>(gp + 98304);
        }
        ull_t a01[4] = {0, 0, 0, 0}, a23[4] = {0, 0, 0, 0};
        #pragma unroll 8
        for (int j = 0; j < 32; j++) {
            int k = kq * 32 + j;
            uint2 wp = *reinterpret_cast<const uint2*>(&S.whh[k][ug * 2]);
            ull_t h01 = *reinterpret_cast<const ull_t*>(&S.hT[k][0]);
            ull_t h23 = *reinterpret_cast<const ull_t*>(&S.hT[k][2]);
            ull_t d0 = pack2(bf_lo(wp.x), bf_lo(wp.x));
            ull_t d1 = pack2(bf_hi(wp.x), bf_hi(wp.x));
            ull_t d2 = pack2(bf_lo(wp.y), bf_lo(wp.y));
            ull_t d3 = pack2(bf_hi(wp.y), bf_hi(wp.y));
            fma2(a01[0], d0, h01); fma2(a23[0], d0, h23);
            fma2(a01[1], d1, h01); fma2(a23[1], d1, h23);
            fma2(a01[2], d2, h01); fma2(a23[2], d2, h23);
            fma2(a01[3], d3, h01); fma2(a23[3], d3, h23);
        }
        float a[16];
        #pragma unroll
        for (int j = 0; j < 4; j++) {
            float2 f01 = unpk(a01[j]), f23 = unpk(a23[j]);
            a[j] = f01.x; a[4 + j] = f01.y; a[8 + j] = f23.x; a[12 + j] = f23.y;
        }
        if (kq) {
            #pragma unroll
            for (int j = 0; j < 16; j++) S.part[kq - 1][j][ug] = a[j];
        }
        __syncthreads();
        if (kq == 0) {
            #pragma unroll
            for (int j = 0; j < 16; j++)
                a[j] += S.part[0][j][ug] + S.part[1][j][ug] + S.part[2][j][ug];
            float nh0, nh1, nh2, nh3;
            {
                float gi = a[0] + gin0.x, gf = a[1] + gin0.y, gg = a[2] + gin0.z, go = a[3] + gin0.w;
                float cv = sig_fast(gf) * c0 + sig_fast(gi) * tanh_fast(gg);
                c0 = cv; nh0 = sig_fast(go) * tanh_fast(cv);
            }
            {
                float gi = a[4] + gin1.x, gf = a[5] + gin1.y, gg = a[6] + gin1.z, go = a[7] + gin1.w;
                float cv = sig_fast(gf) * c1 + sig_fast(gi) * tanh_fast(gg);
                c1 = cv; nh1 = sig_fast(go) * tanh_fast(cv);
            }
            {
                float gi = a[8] + gin2.x, gf = a[9] + gin2.y, gg = a[10] + gin2.z, go = a[11] + gin2.w;
                float cv = sig_fast(gf) * c2 + sig_fast(gi) * tanh_fast(gg);
                c2 = cv; nh2 = sig_fast(go) * tanh_fast(cv);
            }
            {
                float gi = a[12] + gin3.x, gf = a[13] + gin3.y, gg = a[14] + gin3.z, go = a[15] + gin3.w;
                float cv = sig_fast(gf) * c3 + sig_fast(gi) * tanh_fast(gg);
                c3 = cv; nh3 = sig_fast(go) * tanh_fast(cv);
            }
            *reinterpret_cast<float4*>(S.hT[ug]) = make_float4(nh0, nh1, nh2, nh3);
            g_enc[((size_t)(b0 + 0) * TT + t) * HH + ug] = nh0;
            g_enc[((size_t)(b0 + 1) * TT + t) * HH + ug] = nh1;
            g_enc[((size_t)(b0 + 2) * TT + t) * HH + ug] = nh2;
            g_enc[((size_t)(b0 + 3) * TT + t) * HH + ug] = nh3;
        }
        __syncthreads();
    }
}

// ------------------ enc_proj = input_encoded @ W1e^T + dec_b1 (fp32) ------------------
__global__ __launch_bounds__(256) void eproj_gemm(const float* __restrict__ W1,
                                                  const float* __restrict__ b1) {
    __shared__ float As[64][68];
    __shared__ float Ws[64][68];
    int m0 = blockIdx.x * 64;
    int n0 = blockIdx.y * 64;
    int tid = threadIdx.x;
    int tx = tid & 15, ty = tid >> 4;
    float acc[4][4];
    #pragma unroll
    for (int i = 0; i < 4; i++)
        #pragma unroll
        for (int j = 0; j < 4; j++) acc[i][j] = 0.f;
    for (int kc = 0; kc < 2; kc++) {
        __syncthreads();
        #pragma unroll
        for (int i = 0; i < 16; i++) {
            int idx = tid + i * 256;
            int m = idx >> 6, k = idx & 63;
            As[k][m] = g_enc[(size_t)(m0 + m) * HH + kc * 64 + k];
            Ws[k][m] = W1[(n0 + m) * 384 + 256 + kc * 64 + k];
        }
        __syncthreads();
        #pragma unroll 4
        for (int k = 0; k < 64; k++) {
            float4 a = *reinterpret_cast<const float4*>(&As[k][ty * 4]);
            float4 w = *reinterpret_cast<const float4*>(&Ws[k][tx * 4]);
            float av[4] = {a.x, a.y, a.z, a.w};
            float wv[4] = {w.x, w.y, w.z, w.w};
            #pragma unroll
            for (int i = 0; i < 4; i++)
                #pragma unroll
                for (int j = 0; j < 4; j++) acc[i][j] = fmaf(av[i], wv[j], acc[i][j]);
        }
    }
    #pragma unroll
    for (int i = 0; i < 4; i++) {
        int row = m0 + ty * 4 + i;
        #pragma unroll
        for (int j = 0; j < 4; j++) {
            int n = n0 + tx * 4 + j;
            g_eproj[(size_t)row * HH + n] = acc[i][j] + b1[n];
        }
    }
}

// ------------------------- persistent decoder (warp-specialized) -------------------------
// Warps 0-7: gates GEMM.  Warps 8-15: u-proj -> scores -> softmax -> context.
struct DecSmem {
    unsigned int whh[128][256];   // 128 KB
    unsigned int encB[4][64][64]; // 64 KB
    float hcT[256][4];            // rows 0..127 h, 128..255 c
    float partC[16][128];         // gates partials (kh=1)
    float4 partU[128];            // u partials (uh=1)
    float u_s[4][128];
    float ctx_s[4][128];
    float sc[4][64];
    float W2_s[128];
    float fcW_s[128];
    float redy[4][2];
    float xh[4][64];
};

__global__ __launch_bounds__(512) void dec_persist(const float* __restrict__ x,
                                                   const float* __restrict__ dW2,
                                                   const float* __restrict__ fcW,
                                                   const float* __restrict__ fcb,
                                                   const float* __restrict__ fcfW,
                                                   const float* __restrict__ fcfb,
                                                   float* __restrict__ out) {
    extern __shared__ __align__(16) char dec_smem_raw[];
    DecSmem& S = *reinterpret_cast<DecSmem*>(dec_smem_raw);
    int b0 = blockIdx.x * 4;
    int tid = threadIdx.x, lane = tid & 31, wid = tid >> 5;
    int ug = tid & 127;
    float4 wv = make_float4(0.f, 0.f, 0.f, 0.f), bv = wv;
    if (tid < 128) {
        wv = *reinterpret_cast<const float4*>(&g_dWihP[ug * 4]);
        bv = *reinterpret_cast<const float4*>(&g_dbP[ug * 4]);
    }
    // ---- prologue ----
    {
        const uint4* src = reinterpret_cast<const uint4*>(g_WhhB[1]);
        uint4* dst = reinterpret_cast<uint4*>(&S.whh[0][0]);
        for (int i = tid; i < 8192; i += 512) dst[i] = src[i];
    }
    for (int idx = tid; idx < 4 * 64 * 64; idx += 512) {
        int bb = idx >> 12, r = idx & 4095;
        int tt = r >> 6, e2 = r & 63;
        const float* src = g_enc + ((size_t)(b0 + bb) * TT + tt) * HH + 2 * e2;
        S.encB[bb][tt][e2] = pack_bf16x2(src[0], src[1]);
    }
    if (tid < 256) {
        *reinterpret_cast<float4*>(S.hcT[tid]) = make_float4(0.f, 0.f, 0.f, 0.f);
        int bb = tid >> 6, tt = tid & 63;
        S.xh[bb][tt] = x[(size_t)(b0 + bb) * 4096 + tt * 64];
    }
    if (tid < 128) { S.W2_s[tid] = dW2[tid]; S.fcW_s[tid] = fcW[tid]; }
    float fcW128 = fcW[128], fcb0 = fcb[0];
    __syncthreads();

    for (int t = 0; t < 64; t++) {
        float a[16];
        if (tid < 256) {
            // ===== GATES GROUP (warps 0-7): Whh GEMM, k-halves =====
            int kh = tid >> 7;
            ull_t a01[4] = {0, 0, 0, 0}, a23[4] = {0, 0, 0, 0};
            #pragma unroll 8
            for (int j = 0; j < 64; j++) {
                int k = kh * 64 + j;
                uint2 wp = *reinterpret_cast<const uint2*>(&S.whh[k][ug * 2]);
                ull_t h01 = *reinterpret_cast<const ull_t*>(&S.hcT[k][0]);
                ull_t h23 = *reinterpret_cast<const ull_t*>(&S.hcT[k][2]);
                ull_t d0 = pack2(bf_lo(wp.x), bf_lo(wp.x));
                ull_t d1 = pack2(bf_hi(wp.x), bf_hi(wp.x));
                ull_t d2 = pack2(bf_lo(wp.y), bf_lo(wp.y));
                ull_t d3 = pack2(bf_hi(wp.y), bf_hi(wp.y));
                fma2(a01[0], d0, h01); fma2(a23[0], d0, h23);
                fma2(a01[1], d1, h01); fma2(a23[1], d1, h23);
                fma2(a01[2], d2, h01); fma2(a23[2], d2, h23);
                fma2(a01[3], d3, h01); fma2(a23[3], d3, h23);
            }
            #pragma unroll
            for (int j = 0; j < 4; j++) {
                float2 f01 = unpk(a01[j]), f23 = unpk(a23[j]);
                a[j] = f01.x; a[4 + j] = f01.y; a[8 + j] = f23.x; a[12 + j] = f23.y;
            }
            if (kh) {
                #pragma unroll
                for (int j = 0; j < 16; j++) S.partC[j][ug] = a[j];
            }
            BAR_GATE();
            if (kh == 0) {
                #pragma unroll
                for (int j = 0; j < 16; j++) a[j] += S.partC[j][ug];
            }
        } else {
            // ===== ATTN GROUP (warps 8-15) =====
            // --- u-projection (uh: 0=W1h over h, 1=W1c over c) ---
            int uh = (tid >> 7) & 1;
            ull_t u01 = 0, u23 = 0;
            #pragma unroll 8
            for (int j2 = 0; j2 < 64; j2++) {
                int k2 = uh * 64 + j2;
                unsigned int wp = g_W1hcB[k2 * 128 + ug];
                ull_t h0_01 = *reinterpret_cast<const ull_t*>(&S.hcT[2 * k2][0]);
                ull_t h0_23 = *reinterpret_cast<const ull_t*>(&S.hcT[2 * k2][2]);
                ull_t h1_01 = *reinterpret_cast<const ull_t*>(&S.hcT[2 * k2 + 1][0]);
                ull_t h1_23 = *reinterpret_cast<const ull_t*>(&S.hcT[2 * k2 + 1][2]);
                ull_t d0 = pack2(bf_lo(wp), bf_lo(wp));
                ull_t d1 = pack2(bf_hi(wp), bf_hi(wp));
                fma2(u01, d0, h0_01); fma2(u23, d0, h0_23);
                fma2(u01, d1, h1_01); fma2(u23, d1, h1_23);
            }
            if (uh) {
                float2 f0 = unpk(u01), f2 = unpk(u23);
                S.partU[ug] = make_float4(f0.x, f0.y, f2.x, f2.y);
            }
            BAR_ATTN();
            if (!uh) {
                float2 f0 = unpk(u01), f2 = unpk(u23);
                float4 p = S.partU[ug];
                S.u_s[0][ug] = f0.x + p.x;
                S.u_s[1][ug] = f0.y + p.y;
                S.u_s[2][ug] = f2.x + p.z;
                S.u_s[3][ug] = f2.y + p.w;
            }
            BAR_ATTN();
            // --- B1: scores, 32 tasks per warp ---
            int w8 = wid - 8;
            #pragma unroll 8
            for (int it = 0; it < 32; it++) {
                int task = it * 8 + w8;
                int bb = task >> 6, tt = task & 63;
                float4 e4 = *reinterpret_cast<const float4*>(
                    g_eproj + ((size_t)(b0 + bb) * TT + tt) * HH + lane * 4);
                float4 u4 = *reinterpret_cast<const float4*>(&S.u_s[bb][lane * 4]);
                float4 w4 = *reinterpret_cast<const float4*>(&S.W2_s[lane * 4]);
                float p = w4.x * tanh_fast(e4.x + u4.x) + w4.y * tanh_fast(e4.y + u4.y)
                        + w4.z * tanh_fast(e4.z + u4.z) + w4.w * tanh_fast(e4.w + u4.w);
                #pragma unroll
                for (int o = 16; o; o >>= 1) p += __shfl_xor_sync(0xffffffffu, p, o);
                if (lane == 0) S.sc[bb][tt] = p;
            }
            BAR_ATTN();
            // --- B2: softmax (warps 8-11, one per batch) ---
            if (w8 < 4) {
                float s0 = S.sc[w8][lane], s1 = S.sc[w8][lane + 32];
                float m = fmaxf(s0, s1);
                #pragma unroll
                for (int o = 16; o; o >>= 1) m = fmaxf(m, __shfl_xor_sync(0xffffffffu, m, o));
                float e0 = __expf(s0 - m), e1 = __expf(s1 - m);
                float sm = e0 + e1;
                #pragma unroll
                for (int o = 16; o; o >>= 1) sm += __shfl_xor_sync(0xffffffffu, sm, o);
                float inv = 1.0f / sm;
                S.sc[w8][lane] = e0 * inv;
                S.sc[w8][lane + 32] = e1 * inv;
            }
            BAR_ATTN();
            // --- B3: context + y partials (enc bf16 from SMEM) ---
            {
                int bb = (tid >> 6) - 4, e2 = tid & 63;
                float cx0 = 0.f, cx1 = 0.f;
                #pragma unroll 8
                for (int tt = 0; tt < 64; tt++) {
                    float2 f = unpack_bf16x2(S.encB[bb][tt][e2]);
                    float av = S.sc[bb][tt];
                    cx0 = fmaf(av, f.x, cx0);
                    cx1 = fmaf(av, f.y, cx1);
                }
                S.ctx_s[bb][2 * e2] = cx0;
                S.ctx_s[bb][2 * e2 + 1] = cx1;
                float p = cx0 * S.fcW_s[2 * e2] + cx1 * S.fcW_s[2 * e2 + 1];
                #pragma unroll
                for (int o = 16; o; o >>= 1) p += __shfl_xor_sync(0xffffffffu, p, o);
                if (lane == 0) S.redy[bb][(tid >> 5) & 1] = p;
            }
        }
        __syncthreads();
        // ===== epilogue: LSTM cells (tid<128; a[16] in registers) =====
        if (tid < 128) {
            float yv[4];
            #pragma unroll
            for (int b = 0; b < 4; b++)
                yv[b] = S.redy[b][0] + S.redy[b][1] + S.xh[b][t] * fcW128 + fcb0;
            float4 co = *reinterpret_cast<const float4*>(S.hcT[128 + ug]);
            float cvals[4] = {co.x, co.y, co.z, co.w};
            float nh[4], nc[4];
            #pragma unroll
            for (int b = 0; b < 4; b++) {
                float y = yv[b];
                float gi = a[b * 4 + 0] + y * wv.x + bv.x;
                float gf = a[b * 4 + 1] + y * wv.y + bv.y;
                float gg = a[b * 4 + 2] + y * wv.z + bv.z;
                float go = a[b * 4 + 3] + y * wv.w + bv.w;
                float cv = sig_fast(gf) * cvals[b] + sig_fast(gi) * tanh_fast(gg);
                nc[b] = cv;
                nh[b] = sig_fast(go) * tanh_fast(cv);
            }
            *reinterpret_cast<float4*>(S.hcT[128 + ug]) = make_float4(nc[0], nc[1], nc[2], nc[3]);
            *reinterpret_cast<float4*>(S.hcT[ug]) = make_float4(nh[0], nh[1], nh[2], nh[3]);
        }
        __syncthreads();
    }

    // ---- final: out[b] = [h, ctx] @ fcf_W^T + fcf_b ----
    if (tid < 128) {
        int bb = wid;  // 0..3
        float p = 0.f;
        #pragma unroll
        for (int q = 0; q < 4; q++) {
            int e = lane + 32 * q;
            p += S.hcT[e][bb] * fcfW[e] + S.ctx_s[bb][e] * fcfW[128 + e];
        }
        #pragma unroll
        for (int o = 16; o; o >>= 1) p += __shfl_xor_sync(0xffffffffu, p, o);
        if (lane == 0) out[b0 + bb] = p + fcfb[0];
    }
}

// ------------------------- launch -------------------------
extern "C" void kernel_launch(void* const* d_in, const int* in_sizes, int n_in,
                              void* d_out, int out_size) {
    const float* x        = (const float*)d_in[0];
    const float* attnW    = (const float*)d_in[1];
    const float* attnB    = (const float*)d_in[2];
    const float* enc_Wih  = (const float*)d_in[3];
    const float* enc_Whh  = (const float*)d_in[4];
    const float* enc_bih  = (const float*)d_in[5];
    const float* enc_bhh  = (const float*)d_in[6];
    const float* dec_W1   = (const float*)d_in[7];
    const float* dec_b1   = (const float*)d_in[8];
    const float* dec_W2   = (const float*)d_in[9];
    // d_in[10] = dec_b2 (cancels in softmax)
    const float* dec_Wih  = (const float*)d_in[11];
    const float* dec_Whh  = (const float*)d_in[12];
    const float* dec_bih  = (const float*)d_in[13];
    const float* dec_bhh  = (const float*)d_in[14];
    const float* fc_W     = (const float*)d_in[15];
    const float* fc_b     = (const float*)d_in[16];
    const float* fcf_W    = (const float*)d_in[17];
    const float* fcf_b    = (const float*)d_in[18];
    float* out = (float*)d_out;

    int enc_smem = (int)sizeof(EncSmem);
    int dec_smem = (int)sizeof(DecSmem);
    cudaFuncSetAttribute(enc_persist, cudaFuncAttributeMaxDynamicSharedMemorySize, enc_smem);
    cudaFuncSetAttribute(dec_persist, cudaFuncAttributeMaxDynamicSharedMemorySize, dec_smem);

    prep_weights<<<195, 256>>>(enc_Whh, dec_Whh, dec_Wih, dec_bih, dec_bhh, dec_W1);
    prep_attn<<<BB, 64>>>(x, attnW, attnB);
    gin_gemm<<<dim3(BB, 8), 256>>>(x, enc_Wih, enc_bih, enc_bhh);
    enc_persist<<<128, 512, enc_smem>>>();
    eproj_gemm<<<dim3(512, 2), 256>>>(dec_W1, dec_b1);
    dec_persist<<<128, 512, dec_smem>>>(x, dec_W2, fc_W, fc_b, fcf_W, fcf_b, out);
}

// round 13
// speedup vs baseline: 1.2649x; 1.2649x over previous
#include <cuda_runtime.h>
#include <cuda_bf16.h>
#include <math.h>

#define BB 512
#define TT 64
#define NINx 63
#define HH 128

typedef unsigned long long ull_t;

// ------------------------- device scratch (static) -------------------------
__device__ float g_attn[BB * 64];
__device__ float g_gin[(size_t)BB * TT * 512];    // permuted gate order, biases folded
__device__ float g_enc[(size_t)BB * TT * HH];     // input_encoded [b][t][e] fp32
__device__ float g_eproj[(size_t)BB * TT * HH];   // enc_proj (+dec_b1) fp32
__device__ unsigned int g_WhhB[2][128 * 256];     // [enc/dec][k][g/2] bf16x2, permuted
__device__ unsigned int g_W1hcB[128 * 128];       // [k2][e] bf16x2 of (W1h;W1c)^T pairs
__device__ float g_dWihP[512], g_dbP[512];        // permuted dec input weights/biases

__device__ __forceinline__ float tanh_fast(float v) {
    float r; asm("tanh.approx.f32 %0, %1;" : "=f"(r) : "f"(v)); return r;
}
__device__ __forceinline__ float sig_fast(float v) {
    return 0.5f * tanh_fast(0.5f * v) + 0.5f;
}
__device__ __forceinline__ unsigned int pack_bf16x2(float a, float b) {
    __nv_bfloat162 p = __floats2bfloat162_rn(a, b);
    return *reinterpret_cast<unsigned int*>(&p);
}
__device__ __forceinline__ float2 unpack_bf16x2(unsigned int u) {
    return __bfloat1622float2(*reinterpret_cast<__nv_bfloat162*>(&u));
}
// ---- packed f32x2 helpers (Blackwell) ----
__device__ __forceinline__ ull_t pack2(float lo, float hi) {
    ull_t r; asm("mov.b64 %0, {%1, %2};" : "=l"(r) : "f"(lo), "f"(hi)); return r;
}
__device__ __forceinline__ float2 unpk(ull_t v) {
    float2 f; asm("mov.b64 {%0, %1}, %2;" : "=f"(f.x), "=f"(f.y) : "l"(v)); return f;
}
__device__ __forceinline__ void fma2(ull_t& d, ull_t a, ull_t b) {
    asm("fma.rn.f32x2 %0, %1, %2, %0;" : "+l"(d) : "l"(a), "l"(b));
}
__device__ __forceinline__ float bf_lo(unsigned int u) { return __uint_as_float(u << 16); }
__device__ __forceinline__ float bf_hi(unsigned int u) { return __uint_as_float(u & 0xFFFF0000u); }

// ------------------------- weight prep (permute + transpose + bf16) -------------------------
__global__ void prep_weights(const float* __restrict__ eWhh,
                             const float* __restrict__ dWhh,
                             const float* __restrict__ dWih,
                             const float* __restrict__ dbih,
                             const float* __restrict__ dbhh,
                             const float* __restrict__ dW1) {
    int i = blockIdx.x * 256 + threadIdx.x;
    if (i < 32768) {
        int k = i >> 8, g2 = i & 255;
        int gp0 = 2 * g2, gp1 = 2 * g2 + 1;
        int o0 = (gp0 & 3) * HH + (gp0 >> 2);
        int o1 = (gp1 & 3) * HH + (gp1 >> 2);
        g_WhhB[0][k * 256 + g2] = pack_bf16x2(eWhh[o0 * HH + k], eWhh[o1 * HH + k]);
        g_WhhB[1][k * 256 + g2] = pack_bf16x2(dWhh[o0 * HH + k], dWhh[o1 * HH + k]);
    } else if (i < 33280) {
        int gp = i - 32768;
        int orig = (gp & 3) * HH + (gp >> 2);
        g_dWihP[gp] = dWih[orig];
        g_dbP[gp] = dbih[orig] + dbhh[orig];
    } else if (i < 33280 + 16384) {
        int j = i - 33280;
        int e = j & 127, k2 = j >> 7;   // k2 0..127 covers k 0..255 (W1h then W1c)
        g_W1hcB[k2 * 128 + e] = pack_bf16x2(dW1[e * 384 + 2 * k2],
                                            dW1[e * 384 + 2 * k2 + 1]);
    }
}

// ------------------------- encoder attention (time- & state-invariant) -------------------------
__global__ void prep_attn(const float* __restrict__ x,
                          const float* __restrict__ attnW,
                          const float* __restrict__ attnB) {
    __shared__ float s_s[64];
    __shared__ float red[2];
    int b = blockIdx.x, n = threadIdx.x;
    float s = -1e30f;
    if (n < NINx) {
        float acc = attnB[0];
        const float* wt = attnW + 2 * HH;
        #pragma unroll 8
        for (int t = 0; t < TT; t++) acc = fmaf(x[b * 4096 + t * 64 + n + 1], wt[t], acc);
        s = acc;
    }
    s_s[n] = s;
    __syncthreads();
    if (n < 32) {
        float m = fmaxf(s_s[n], s_s[n + 32]);
        #pragma unroll
        for (int o = 16; o; o >>= 1) m = fmaxf(m, __shfl_xor_sync(0xffffffffu, m, o));
        if (n == 0) red[0] = m;
    }
    __syncthreads();
    float e = (n < NINx) ? expf(s - red[0]) : 0.f;
    s_s[n] = e;
    __syncthreads();
    if (n < 32) {
        float sm = s_s[n] + s_s[n + 32];
        #pragma unroll
        for (int o = 16; o; o >>= 1) sm += __shfl_xor_sync(0xffffffffu, sm, o);
        if (n == 0) red[1] = sm;
    }
    __syncthreads();
    if (n < 64) g_attn[b * 64 + n] = (n < NINx) ? e / red[1] : 0.f;
}

// ------------- gin[b,t,g'] = sum_n attn[b,n]*x[b,t,n+1]*Wih[orig(g'),n] + bias -------------
__global__ __launch_bounds__(256) void gin_gemm(const float* __restrict__ x,
                                                const float* __restrict__ Wih,
                                                const float* __restrict__ bih,
                                                const float* __restrict__ bhh) {
    __shared__ float attn_s[64];
    __shared__ float As[64][68];
    __shared__ float Ws[64][68];
    int bb = blockIdx.x;
    int g0 = blockIdx.y * 64;
    int tid = threadIdx.x;
    if (tid < 64) attn_s[tid] = g_attn[bb * 64 + tid];
    __syncthreads();
    #pragma unroll
    for (int i = 0; i < 16; i++) {
        int idx = tid + i * 256;
        int m = idx >> 6, k = idx & 63;
        As[k][m] = (k < NINx) ? attn_s[k] * x[bb * 4096 + m * 64 + k + 1] : 0.f;
        int gp = g0 + m;
        int orig = (gp & 3) * HH + (gp >> 2);
        Ws[k][m] = (k < NINx) ? Wih[orig * NINx + k] : 0.f;
    }
    __syncthreads();
    int tx = tid & 15, ty = tid >> 4;
    ull_t acc2[4][2];
    #pragma unroll
    for (int i = 0; i < 4; i++) { acc2[i][0] = 0; acc2[i][1] = 0; }
    #pragma unroll 4
    for (int k = 0; k < 64; k++) {
        float4 a = *reinterpret_cast<const float4*>(&As[k][ty * 4]);
        ull_t w01 = *reinterpret_cast<const ull_t*>(&Ws[k][tx * 4]);
        ull_t w23 = *reinterpret_cast<const ull_t*>(&Ws[k][tx * 4 + 2]);
        ull_t a0 = pack2(a.x, a.x), a1 = pack2(a.y, a.y);
        ull_t a2 = pack2(a.z, a.z), a3 = pack2(a.w, a.w);
        fma2(acc2[0][0], a0, w01); fma2(acc2[0][1], a0, w23);
        fma2(acc2[1][0], a1, w01); fma2(acc2[1][1], a1, w23);
        fma2(acc2[2][0], a2, w01); fma2(acc2[2][1], a2, w23);
        fma2(acc2[3][0], a3, w01); fma2(acc2[3][1], a3, w23);
    }
    #pragma unroll
    for (int i = 0; i < 4; i++) {
        int t = ty * 4 + i;
        float2 j01 = unpk(acc2[i][0]), j23 = unpk(acc2[i][1]);
        float accv[4] = {j01.x, j01.y, j23.x, j23.y};
        #pragma unroll
        for (int j = 0; j < 4; j++) {
            int gp = g0 + tx * 4 + j;
            int orig = (gp & 3) * HH + (gp >> 2);
            g_gin[((size_t)bb * TT + t) * 512 + gp] = accv[j] + bih[orig] + bhh[orig];
        }
    }
}

// ------------------------- persistent encoder: 128 blocks x 4 batches, 64 steps -------------------------
struct EncSmem {
    unsigned int whh[128][256];   // bf16x2 [k][g/2]   128 KB
    float hT[128][4];             // [unit][batch]
    float part[3][16][128];       // partials from kq=1..3
};

__global__ __launch_bounds__(512) void enc_persist() {
    extern __shared__ __align__(16) char enc_smem_raw[];
    EncSmem& S = *reinterpret_cast<EncSmem*>(enc_smem_raw);
    int b0 = blockIdx.x * 4;
    int tid = threadIdx.x;
    int ug = tid & 127, kq = tid >> 7;
    {
        const uint4* src = reinterpret_cast<const uint4*>(g_WhhB[0]);
        uint4* dst = reinterpret_cast<uint4*>(&S.whh[0][0]);
        for (int i = tid; i < 8192; i += 512) dst[i] = src[i];
    }
    if (tid < 128) *reinterpret_cast<float4*>(S.hT[tid]) = make_float4(0.f, 0.f, 0.f, 0.f);
    float c0 = 0.f, c1 = 0.f, c2 = 0.f, c3 = 0.f;
    __syncthreads();
    for (int t = 0; t < 64; t++) {
        float4 gin0, gin1, gin2, gin3;
        if (kq == 0) {
            const float* gp = g_gin + ((size_t)b0 * 64 + t) * 512 + ug * 4;
            gin0 = *reinterpret_cast<const float4*>(gp);
            gin1 = *reinterpret_cast<const float4*>(gp + 32768);
            gin2 = *reinterpret_cast<const float4*>(gp + 65536);
            gin3 = *reinterpret_cast<const float4*>(gp + 98304);
        }
        ull_t a01[4] = {0, 0, 0, 0}, a23[4] = {0, 0, 0, 0};
        #pragma unroll 8
        for (int j = 0; j < 32; j++) {
            int k = kq * 32 + j;
            uint2 wp = *reinterpret_cast<const uint2*>(&S.whh[k][ug * 2]);
            ull_t h01 = *reinterpret_cast<const ull_t*>(&S.hT[k][0]);
            ull_t h23 = *reinterpret_cast<const ull_t*>(&S.hT[k][2]);
            ull_t d0 = pack2(bf_lo(wp.x), bf_lo(wp.x));
            ull_t d1 = pack2(bf_hi(wp.x), bf_hi(wp.x));
            ull_t d2 = pack2(bf_lo(wp.y), bf_lo(wp.y));
            ull_t d3 = pack2(bf_hi(wp.y), bf_hi(wp.y));
            fma2(a01[0], d0, h01); fma2(a23[0], d0, h23);
            fma2(a01[1], d1, h01); fma2(a23[1], d1, h23);
            fma2(a01[2], d2, h01); fma2(a23[2], d2, h23);
            fma2(a01[3], d3, h01); fma2(a23[3], d3, h23);
        }
        float a[16];
        #pragma unroll
        for (int j = 0; j < 4; j++) {
            float2 f01 = unpk(a01[j]), f23 = unpk(a23[j]);
            a[j] = f01.x; a[4 + j] = f01.y; a[8 + j] = f23.x; a[12 + j] = f23.y;
        }
        if (kq) {
            #pragma unroll
            for (int j = 0; j < 16; j++) S.part[kq - 1][j][ug] = a[j];
        }
        __syncthreads();
        if (kq == 0) {
            #pragma unroll
            for (int j = 0; j < 16; j++)
                a[j] += S.part[0][j][ug] + S.part[1][j][ug] + S.part[2][j][ug];
            float nh0, nh1, nh2, nh3;
            {
                float gi = a[0] + gin0.x, gf = a[1] + gin0.y, gg = a[2] + gin0.z, go = a[3] + gin0.w;
                float cv = sig_fast(gf) * c0 + sig_fast(gi) * tanh_fast(gg);
                c0 = cv; nh0 = sig_fast(go) * tanh_fast(cv);
            }
            {
                float gi = a[4] + gin1.x, gf = a[5] + gin1.y, gg = a[6] + gin1.z, go = a[7] + gin1.w;
                float cv = sig_fast(gf) * c1 + sig_fast(gi) * tanh_fast(gg);
                c1 = cv; nh1 = sig_fast(go) * tanh_fast(cv);
            }
            {
                float gi = a[8] + gin2.x, gf = a[9] + gin2.y, gg = a[10] + gin2.z, go = a[11] + gin2.w;
                float cv = sig_fast(gf) * c2 + sig_fast(gi) * tanh_fast(gg);
                c2 = cv; nh2 = sig_fast(go) * tanh_fast(cv);
            }
            {
                float gi = a[12] + gin3.x, gf = a[13] + gin3.y, gg = a[14] + gin3.z, go = a[15] + gin3.w;
                float cv = sig_fast(gf) * c3 + sig_fast(gi) * tanh_fast(gg);
                c3 = cv; nh3 = sig_fast(go) * tanh_fast(cv);
            }
            *reinterpret_cast<float4*>(S.hT[ug]) = make_float4(nh0, nh1, nh2, nh3);
            g_enc[((size_t)(b0 + 0) * TT + t) * HH + ug] = nh0;
            g_enc[((size_t)(b0 + 1) * TT + t) * HH + ug] = nh1;
            g_enc[((size_t)(b0 + 2) * TT + t) * HH + ug] = nh2;
            g_enc[((size_t)(b0 + 3) * TT + t) * HH + ug] = nh3;
        }
        __syncthreads();
    }
}

// ------------------ enc_proj = input_encoded @ W1e^T + dec_b1 (fp32, f32x2 math) ------------------
__global__ __launch_bounds__(256) void eproj_gemm(const float* __restrict__ W1,
                                                  const float* __restrict__ b1) {
    __shared__ float As[64][68];
    __shared__ float Ws[64][68];
    int m0 = blockIdx.x * 64;
    int n0 = blockIdx.y * 64;
    int tid = threadIdx.x;
    int tx = tid & 15, ty = tid >> 4;
    ull_t acc2[4][2];
    #pragma unroll
    for (int i = 0; i < 4; i++) { acc2[i][0] = 0; acc2[i][1] = 0; }
    for (int kc = 0; kc < 2; kc++) {
        __syncthreads();
        #pragma unroll
        for (int i = 0; i < 16; i++) {
            int idx = tid + i * 256;
            int m = idx >> 6, k = idx & 63;
            As[k][m] = g_enc[(size_t)(m0 + m) * HH + kc * 64 + k];
            Ws[k][m] = W1[(n0 + m) * 384 + 256 + kc * 64 + k];
        }
        __syncthreads();
        #pragma unroll 4
        for (int k = 0; k < 64; k++) {
            float4 a = *reinterpret_cast<const float4*>(&As[k][ty * 4]);
            ull_t w01 = *reinterpret_cast<const ull_t*>(&Ws[k][tx * 4]);
            ull_t w23 = *reinterpret_cast<const ull_t*>(&Ws[k][tx * 4 + 2]);
            ull_t a0 = pack2(a.x, a.x), a1 = pack2(a.y, a.y);
            ull_t a2 = pack2(a.z, a.z), a3 = pack2(a.w, a.w);
            fma2(acc2[0][0], a0, w01); fma2(acc2[0][1], a0, w23);
            fma2(acc2[1][0], a1, w01); fma2(acc2[1][1], a1, w23);
            fma2(acc2[2][0], a2, w01); fma2(acc2[2][1], a2, w23);
            fma2(acc2[3][0], a3, w01); fma2(acc2[3][1], a3, w23);
        }
    }
    #pragma unroll
    for (int i = 0; i < 4; i++) {
        int row = m0 + ty * 4 + i;
        float2 j01 = unpk(acc2[i][0]), j23 = unpk(acc2[i][1]);
        float accv[4] = {j01.x, j01.y, j23.x, j23.y};
        #pragma unroll
        for (int j = 0; j < 4; j++) {
            int n = n0 + tx * 4 + j;
            g_eproj[(size_t)row * HH + n] = accv[j] + b1[n];
        }
    }
}

// ------------------------- persistent decoder: 128 blocks x 4 batches, 64 steps -------------------------
// 512 threads. whh (bf16, 128K) + enc (bf16, 64K) smem-resident.
// Phase G split: warps 0-7 gates GEMM (k-halves), warps 8-15 u GEMM (h-half / c-half).
struct DecSmem {
    unsigned int whh[128][256];   // 128 KB
    unsigned int encB[4][64][64]; // 64 KB  [bb][tt][e/2] bf16x2
    float hcT[256][4];            // 4 KB: rows 0..127 h, 128..255 c
    float partC[16][128];         // 8 KB  gates partials (kh=1)
    float4 partU[128];            // 2 KB  u partials (uh=1)
    float u_s[4][128];
    float ctx_s[4][128];
    float sc[4][64];
    float W2_s[128];
    float fcW_s[128];
    float redy[4][2];
    float xh[4][64];
};

__global__ __launch_bounds__(512) void dec_persist(const float* __restrict__ x,
                                                   const float* __restrict__ dW2,
                                                   const float* __restrict__ fcW,
                                                   const float* __restrict__ fcb,
                                                   const float* __restrict__ fcfW,
                                                   const float* __restrict__ fcfb,
                                                   float* __restrict__ out) {
    extern __shared__ __align__(16) char dec_smem_raw[];
    DecSmem& S = *reinterpret_cast<DecSmem*>(dec_smem_raw);
    int b0 = blockIdx.x * 4;
    int tid = threadIdx.x, lane = tid & 31, wid = tid >> 5;
    int ug = tid & 127;
    float4 wv = make_float4(0.f, 0.f, 0.f, 0.f), bv = wv;
    if (tid < 128) {
        wv = *reinterpret_cast<const float4*>(&g_dWihP[ug * 4]);
        bv = *reinterpret_cast<const float4*>(&g_dbP[ug * 4]);
    }
    // ---- prologue ----
    {
        const uint4* src = reinterpret_cast<const uint4*>(g_WhhB[1]);
        uint4* dst = reinterpret_cast<uint4*>(&S.whh[0][0]);
        for (int i = tid; i < 8192; i += 512) dst[i] = src[i];
    }
    for (int idx = tid; idx < 4 * 64 * 64; idx += 512) {
        int bb = idx >> 12, r = idx & 4095;
        int tt = r >> 6, e2 = r & 63;
        const float* src = g_enc + ((size_t)(b0 + bb) * TT + tt) * HH + 2 * e2;
        S.encB[bb][tt][e2] = pack_bf16x2(src[0], src[1]);
    }
    if (tid < 256) {
        *reinterpret_cast<float4*>(S.hcT[tid]) = make_float4(0.f, 0.f, 0.f, 0.f);
        int bb = tid >> 6, tt = tid & 63;
        S.xh[bb][tt] = x[(size_t)(b0 + bb) * 4096 + tt * 64];
    }
    if (tid < 128) { S.W2_s[tid] = dW2[tid]; S.fcW_s[tid] = fcW[tid]; }
    float fcW128 = fcW[128], fcb0 = fcb[0];
    __syncthreads();

    for (int t = 0; t < 64; t++) {
        // ===== phase G: warps 0-7 gates GEMM, warps 8-15 u GEMM =====
        float a[16];
        ull_t u01 = 0, u23 = 0;
        if (tid < 256) {
            int kh = tid >> 7;   // k-half
            ull_t a01[4] = {0, 0, 0, 0}, a23[4] = {0, 0, 0, 0};
            #pragma unroll 8
            for (int j = 0; j < 64; j++) {
                int k = kh * 64 + j;
                uint2 wp = *reinterpret_cast<const uint2*>(&S.whh[k][ug * 2]);
                ull_t h01 = *reinterpret_cast<const ull_t*>(&S.hcT[k][0]);
                ull_t h23 = *reinterpret_cast<const ull_t*>(&S.hcT[k][2]);
                ull_t d0 = pack2(bf_lo(wp.x), bf_lo(wp.x));
                ull_t d1 = pack2(bf_hi(wp.x), bf_hi(wp.x));
                ull_t d2 = pack2(bf_lo(wp.y), bf_lo(wp.y));
                ull_t d3 = pack2(bf_hi(wp.y), bf_hi(wp.y));
                fma2(a01[0], d0, h01); fma2(a23[0], d0, h23);
                fma2(a01[1], d1, h01); fma2(a23[1], d1, h23);
                fma2(a01[2], d2, h01); fma2(a23[2], d2, h23);
                fma2(a01[3], d3, h01); fma2(a23[3], d3, h23);
            }
            #pragma unroll
            for (int j = 0; j < 4; j++) {
                float2 f01 = unpk(a01[j]), f23 = unpk(a23[j]);
                a[j] = f01.x; a[4 + j] = f01.y; a[8 + j] = f23.x; a[12 + j] = f23.y;
            }
            if (kh) {
                #pragma unroll
                for (int j = 0; j < 16; j++) S.partC[j][ug] = a[j];
            }
        } else {
            int uh = (tid >> 7) & 1;  // 0: W1h over h, 1: W1c over c
            #pragma unroll 8
            for (int j2 = 0; j2 < 64; j2++) {
                int k2 = uh * 64 + j2;
                unsigned int wp = g_W1hcB[k2 * 128 + ug];
                ull_t h0_01 = *reinterpret_cast<const ull_t*>(&S.hcT[2 * k2][0]);
                ull_t h0_23 = *reinterpret_cast<const ull_t*>(&S.hcT[2 * k2][2]);
                ull_t h1_01 = *reinterpret_cast<const ull_t*>(&S.hcT[2 * k2 + 1][0]);
                ull_t h1_23 = *reinterpret_cast<const ull_t*>(&S.hcT[2 * k2 + 1][2]);
                ull_t d0 = pack2(bf_lo(wp), bf_lo(wp));
                ull_t d1 = pack2(bf_hi(wp), bf_hi(wp));
                fma2(u01, d0, h0_01); fma2(u23, d0, h0_23);
                fma2(u01, d1, h1_01); fma2(u23, d1, h1_23);
            }
            if (uh) {
                float2 f0 = unpk(u01), f2 = unpk(u23);
                S.partU[ug] = make_float4(f0.x, f0.y, f2.x, f2.y);
            }
        }
        __syncthreads();
        // combine: tid<128 gates into regs; warps 8-11 combine u into u_s
        if (tid < 128) {
            #pragma unroll
            for (int j = 0; j < 16; j++) a[j] += S.partC[j][ug];
        } else if ((tid >> 7) == 2) {
            float2 f0 = unpk(u01), f2 = unpk(u23);
            float4 p = S.partU[ug];
            S.u_s[0][ug] = f0.x + p.x;
            S.u_s[1][ug] = f0.y + p.y;
            S.u_s[2][ug] = f2.x + p.z;
            S.u_s[3][ug] = f2.y + p.w;
        }
        __syncthreads();
        // ===== phase B1: scores (warp per (batch,t'); eproj fp32 from L2, MLP 8) =====
        #pragma unroll 8
        for (int it = 0; it < 16; it++) {
            int task = it * 16 + wid;
            int bb = task >> 6, tt = task & 63;
            float4 e4 = *reinterpret_cast<const float4*>(
                g_eproj + ((size_t)(b0 + bb) * TT + tt) * HH + lane * 4);
            float4 u4 = *reinterpret_cast<const float4*>(&S.u_s[bb][lane * 4]);
            float4 w4 = *reinterpret_cast<const float4*>(&S.W2_s[lane * 4]);
            float p = w4.x * tanh_fast(e4.x + u4.x) + w4.y * tanh_fast(e4.y + u4.y)
                    + w4.z * tanh_fast(e4.z + u4.z) + w4.w * tanh_fast(e4.w + u4.w);
            #pragma unroll
            for (int o = 16; o; o >>= 1) p += __shfl_xor_sync(0xffffffffu, p, o);
            if (lane == 0) S.sc[bb][tt] = p;
        }
        __syncthreads();
        // ===== phase B2: softmax (warps 4-7, one per batch) =====
        if (wid >= 4 && wid < 8) {
            int bb = wid - 4;
            float s0 = S.sc[bb][lane], s1 = S.sc[bb][lane + 32];
            float m = fmaxf(s0, s1);
            #pragma unroll
            for (int o = 16; o; o >>= 1) m = fmaxf(m, __shfl_xor_sync(0xffffffffu, m, o));
            float e0 = __expf(s0 - m), e1 = __expf(s1 - m);
            float sm = e0 + e1;
            #pragma unroll
            for (int o = 16; o; o >>= 1) sm += __shfl_xor_sync(0xffffffffu, sm, o);
            float inv = 1.0f / sm;
            S.sc[bb][lane] = e0 * inv;
            S.sc[bb][lane + 32] = e1 * inv;
        }
        __syncthreads();
        // ===== phase B3: context + y partials (tid<256; enc bf16 from SMEM) =====
        if (tid < 256) {
            int bb = tid >> 6, e2 = tid & 63;
            float cx0 = 0.f, cx1 = 0.f;
            #pragma unroll 8
            for (int tt = 0; tt < 64; tt++) {
                float2 f = unpack_bf16x2(S.encB[bb][tt][e2]);
                float av = S.sc[bb][tt];
                cx0 = fmaf(av, f.x, cx0);
                cx1 = fmaf(av, f.y, cx1);
            }
            S.ctx_s[bb][2 * e2] = cx0;
            S.ctx_s[bb][2 * e2 + 1] = cx1;
            float p = cx0 * S.fcW_s[2 * e2] + cx1 * S.fcW_s[2 * e2 + 1];
            #pragma unroll
            for (int o = 16; o; o >>= 1) p += __shfl_xor_sync(0xffffffffu, p, o);
            if (lane == 0) S.redy[bb][(tid >> 5) & 1] = p;
        }
        __syncthreads();
        // ===== epilogue: LSTM cells (tid<128; a[16] in registers) =====
        if (tid < 128) {
            float yv[4];
            #pragma unroll
            for (int b = 0; b < 4; b++)
                yv[b] = S.redy[b][0] + S.redy[b][1] + S.xh[b][t] * fcW128 + fcb0;
            float4 co = *reinterpret_cast<const float4*>(S.hcT[128 + ug]);
            float cvals[4] = {co.x, co.y, co.z, co.w};
            float nh[4], nc[4];
            #pragma unroll
            for (int b = 0; b < 4; b++) {
                float y = yv[b];
                float gi = a[b * 4 + 0] + y * wv.x + bv.x;
                float gf = a[b * 4 + 1] + y * wv.y + bv.y;
                float gg = a[b * 4 + 2] + y * wv.z + bv.z;
                float go = a[b * 4 + 3] + y * wv.w + bv.w;
                float cv = sig_fast(gf) * cvals[b] + sig_fast(gi) * tanh_fast(gg);
                nc[b] = cv;
                nh[b] = sig_fast(go) * tanh_fast(cv);
            }
            *reinterpret_cast<float4*>(S.hcT[128 + ug]) = make_float4(nc[0], nc[1], nc[2], nc[3]);
            *reinterpret_cast<float4*>(S.hcT[ug]) = make_float4(nh[0], nh[1], nh[2], nh[3]);
        }
        __syncthreads();
    }

    // ---- final: out[b] = [h, ctx] @ fcf_W^T + fcf_b ----
    if (tid < 128) {
        int bb = wid;  // 0..3
        float p = 0.f;
        #pragma unroll
        for (int q = 0; q < 4; q++) {
            int e = lane + 32 * q;
            p += S.hcT[e][bb] * fcfW[e] + S.ctx_s[bb][e] * fcfW[128 + e];
        }
        #pragma unroll
        for (int o = 16; o; o >>= 1) p += __shfl_xor_sync(0xffffffffu, p, o);
        if (lane == 0) out[b0 + bb] = p + fcfb[0];
    }
}

// ------------------------- launch -------------------------
extern "C" void kernel_launch(void* const* d_in, const int* in_sizes, int n_in,
                              void* d_out, int out_size) {
    const float* x        = (const float*)d_in[0];
    const float* attnW    = (const float*)d_in[1];
    const float* attnB    = (const float*)d_in[2];
    const float* enc_Wih  = (const float*)d_in[3];
    const float* enc_Whh  = (const float*)d_in[4];
    const float* enc_bih  = (const float*)d_in[5];
    const float* enc_bhh  = (const float*)d_in[6];
    const float* dec_W1   = (const float*)d_in[7];
    const float* dec_b1   = (const float*)d_in[8];
    const float* dec_W2   = (const float*)d_in[9];
    // d_in[10] = dec_b2 (cancels in softmax)
    const float* dec_Wih  = (const float*)d_in[11];
    const float* dec_Whh  = (const float*)d_in[12];
    const float* dec_bih  = (const float*)d_in[13];
    const float* dec_bhh  = (const float*)d_in[14];
    const float* fc_W     = (const float*)d_in[15];
    const float* fc_b     = (const float*)d_in[16];
    const float* fcf_W    = (const float*)d_in[17];
    const float* fcf_b    = (const float*)d_in[18];
    float* out = (float*)d_out;

    int enc_smem = (int)sizeof(EncSmem);
    int dec_smem = (int)sizeof(DecSmem);
    cudaFuncSetAttribute(enc_persist, cudaFuncAttributeMaxDynamicSharedMemorySize, enc_smem);
    cudaFuncSetAttribute(dec_persist, cudaFuncAttributeMaxDynamicSharedMemorySize, dec_smem);

    prep_weights<<<195, 256>>>(enc_Whh, dec_Whh, dec_Wih, dec_bih, dec_bhh, dec_W1);
    prep_attn<<<BB, 64>>>(x, attnW, attnB);
    gin_gemm<<<dim3(BB, 8), 256>>>(x, enc_Wih, enc_bih, enc_bhh);
    enc_persist<<<128, 512, enc_smem>>>();
    eproj_gemm<<<dim3(512, 2), 256>>>(dec_W1, dec_b1);
    dec_persist<<<128, 512, dec_smem>>>(x, dec_W2, fc_W, fc_b, fcf_W, fcf_b, out);
}

// round 14
// speedup vs baseline: 1.2659x; 1.0007x over previous
#include <cuda_runtime.h>
#include <cuda_bf16.h>
#include <math.h>

#define BB 512
#define TT 64
#define NINx 63
#define HH 128

typedef unsigned long long ull_t;

// ------------------------- device scratch (static) -------------------------
__device__ float g_attn[BB * 64];
__device__ float g_gin[(size_t)BB * TT * 512];    // permuted gate order, biases folded
__device__ float g_enc[(size_t)BB * TT * HH];     // input_encoded [b][t][e] fp32
__device__ float g_eproj[(size_t)BB * TT * HH];   // enc_proj (+dec_b1) fp32
__device__ unsigned int g_WhhB[2][128 * 256];     // [enc/dec][k][g/2] bf16x2, permuted
__device__ unsigned int g_W1hcB[128 * 128];       // [k2][e] bf16x2 of (W1h;W1c)^T pairs
__device__ float g_dWihP[512], g_dbP[512];        // permuted dec input weights/biases

__device__ __forceinline__ float tanh_fast(float v) {
    float r; asm("tanh.approx.f32 %0, %1;" : "=f"(r) : "f"(v)); return r;
}
__device__ __forceinline__ float sig_fast(float v) {
    return 0.5f * tanh_fast(0.5f * v) + 0.5f;
}
__device__ __forceinline__ unsigned int pack_bf16x2(float a, float b) {
    __nv_bfloat162 p = __floats2bfloat162_rn(a, b);
    return *reinterpret_cast<unsigned int*>(&p);
}
__device__ __forceinline__ float2 unpack_bf16x2(unsigned int u) {
    return __bfloat1622float2(*reinterpret_cast<__nv_bfloat162*>(&u));
}
// ---- packed f32x2 helpers (Blackwell) ----
__device__ __forceinline__ ull_t pack2(float lo, float hi) {
    ull_t r; asm("mov.b64 %0, {%1, %2};" : "=l"(r) : "f"(lo), "f"(hi)); return r;
}
__device__ __forceinline__ float2 unpk(ull_t v) {
    float2 f; asm("mov.b64 {%0, %1}, %2;" : "=f"(f.x), "=f"(f.y) : "l"(v)); return f;
}
__device__ __forceinline__ void fma2(ull_t& d, ull_t a, ull_t b) {
    asm("fma.rn.f32x2 %0, %1, %2, %0;" : "+l"(d) : "l"(a), "l"(b));
}
__device__ __forceinline__ float bf_lo(unsigned int u) { return __uint_as_float(u << 16); }
__device__ __forceinline__ float bf_hi(unsigned int u) { return __uint_as_float(u & 0xFFFF0000u); }

// ------------------------- weight prep (permute + transpose + bf16) -------------------------
__global__ void prep_weights(const float* __restrict__ eWhh,
                             const float* __restrict__ dWhh,
                             const float* __restrict__ dWih,
                             const float* __restrict__ dbih,
                             const float* __restrict__ dbhh,
                             const float* __restrict__ dW1) {
    int i = blockIdx.x * 256 + threadIdx.x;
    if (i < 32768) {
        int k = i >> 8, g2 = i & 255;
        int gp0 = 2 * g2, gp1 = 2 * g2 + 1;
        int o0 = (gp0 & 3) * HH + (gp0 >> 2);
        int o1 = (gp1 & 3) * HH + (gp1 >> 2);
        g_WhhB[0][k * 256 + g2] = pack_bf16x2(eWhh[o0 * HH + k], eWhh[o1 * HH + k]);
        g_WhhB[1][k * 256 + g2] = pack_bf16x2(dWhh[o0 * HH + k], dWhh[o1 * HH + k]);
    } else if (i < 33280) {
        int gp = i - 32768;
        int orig = (gp & 3) * HH + (gp >> 2);
        g_dWihP[gp] = dWih[orig];
        g_dbP[gp] = dbih[orig] + dbhh[orig];
    } else if (i < 33280 + 16384) {
        int j = i - 33280;
        int e = j & 127, k2 = j >> 7;   // k2 0..127 covers k 0..255 (W1h then W1c)
        g_W1hcB[k2 * 128 + e] = pack_bf16x2(dW1[e * 384 + 2 * k2],
                                            dW1[e * 384 + 2 * k2 + 1]);
    }
}

// ------------------------- encoder attention (time- & state-invariant) -------------------------
__global__ void prep_attn(const float* __restrict__ x,
                          const float* __restrict__ attnW,
                          const float* __restrict__ attnB) {
    __shared__ float s_s[64];
    __shared__ float red[2];
    int b = blockIdx.x, n = threadIdx.x;
    float s = -1e30f;
    if (n < NINx) {
        float acc = attnB[0];
        const float* wt = attnW + 2 * HH;
        #pragma unroll 8
        for (int t = 0; t < TT; t++) acc = fmaf(x[b * 4096 + t * 64 + n + 1], wt[t], acc);
        s = acc;
    }
    s_s[n] = s;
    __syncthreads();
    if (n < 32) {
        float m = fmaxf(s_s[n], s_s[n + 32]);
        #pragma unroll
        for (int o = 16; o; o >>= 1) m = fmaxf(m, __shfl_xor_sync(0xffffffffu, m, o));
        if (n == 0) red[0] = m;
    }
    __syncthreads();
    float e = (n < NINx) ? expf(s - red[0]) : 0.f;
    s_s[n] = e;
    __syncthreads();
    if (n < 32) {
        float sm = s_s[n] + s_s[n + 32];
        #pragma unroll
        for (int o = 16; o; o >>= 1) sm += __shfl_xor_sync(0xffffffffu, sm, o);
        if (n == 0) red[1] = sm;
    }
    __syncthreads();
    if (n < 64) g_attn[b * 64 + n] = (n < NINx) ? e / red[1] : 0.f;
}

// ------------- gin[b,t,g'] = sum_n attn[b,n]*x[b,t,n+1]*Wih[orig(g'),n] + bias -------------
__global__ __launch_bounds__(256) void gin_gemm(const float* __restrict__ x,
                                                const float* __restrict__ Wih,
                                                const float* __restrict__ bih,
                                                const float* __restrict__ bhh) {
    __shared__ float attn_s[64];
    __shared__ float As[64][68];
    __shared__ float Ws[64][68];
    int bb = blockIdx.x;
    int g0 = blockIdx.y * 64;
    int tid = threadIdx.x;
    if (tid < 64) attn_s[tid] = g_attn[bb * 64 + tid];
    __syncthreads();
    #pragma unroll
    for (int i = 0; i < 16; i++) {
        int idx = tid + i * 256;
        int m = idx >> 6, k = idx & 63;
        As[k][m] = (k < NINx) ? attn_s[k] * x[bb * 4096 + m * 64 + k + 1] : 0.f;
        int gp = g0 + m;
        int orig = (gp & 3) * HH + (gp >> 2);
        Ws[k][m] = (k < NINx) ? Wih[orig * NINx + k] : 0.f;
    }
    __syncthreads();
    int tx = tid & 15, ty = tid >> 4;
    ull_t acc2[4][2];
    #pragma unroll
    for (int i = 0; i < 4; i++) { acc2[i][0] = 0; acc2[i][1] = 0; }
    #pragma unroll 4
    for (int k = 0; k < 64; k++) {
        float4 a = *reinterpret_cast<const float4*>(&As[k][ty * 4]);
        ull_t w01 = *reinterpret_cast<const ull_t*>(&Ws[k][tx * 4]);
        ull_t w23 = *reinterpret_cast<const ull_t*>(&Ws[k][tx * 4 + 2]);
        ull_t a0 = pack2(a.x, a.x), a1 = pack2(a.y, a.y);
        ull_t a2 = pack2(a.z, a.z), a3 = pack2(a.w, a.w);
        fma2(acc2[0][0], a0, w01); fma2(acc2[0][1], a0, w23);
        fma2(acc2[1][0], a1, w01); fma2(acc2[1][1], a1, w23);
        fma2(acc2[2][0], a2, w01); fma2(acc2[2][1], a2, w23);
        fma2(acc2[3][0], a3, w01); fma2(acc2[3][1], a3, w23);
    }
    #pragma unroll
    for (int i = 0; i < 4; i++) {
        int t = ty * 4 + i;
        float2 j01 = unpk(acc2[i][0]), j23 = unpk(acc2[i][1]);
        float accv[4] = {j01.x, j01.y, j23.x, j23.y};
        #pragma unroll
        for (int j = 0; j < 4; j++) {
            int gp = g0 + tx * 4 + j;
            int orig = (gp & 3) * HH + (gp >> 2);
            g_gin[((size_t)bb * TT + t) * 512 + gp] = accv[j] + bih[orig] + bhh[orig];
        }
    }
}

// ------------------------- persistent encoder: 128 blocks x 4 batches, 64 steps -------------------------
struct EncSmem {
    unsigned int whh[128][256];   // bf16x2 [k][g/2]   128 KB
    float hT[128][4];             // [unit][batch]
    float part[3][16][128];       // partials from kq=1..3
};

__global__ __launch_bounds__(512) void enc_persist() {
    extern __shared__ __align__(16) char enc_smem_raw[];
    EncSmem& S = *reinterpret_cast<EncSmem*>(enc_smem_raw);
    int b0 = blockIdx.x * 4;
    int tid = threadIdx.x;
    int ug = tid & 127, kq = tid >> 7;
    {
        const uint4* src = reinterpret_cast<const uint4*>(g_WhhB[0]);
        uint4* dst = reinterpret_cast<uint4*>(&S.whh[0][0]);
        for (int i = tid; i < 8192; i += 512) dst[i] = src[i];
    }
    if (tid < 128) *reinterpret_cast<float4*>(S.hT[tid]) = make_float4(0.f, 0.f, 0.f, 0.f);
    float c0 = 0.f, c1 = 0.f, c2 = 0.f, c3 = 0.f;
    __syncthreads();
    for (int t = 0; t < 64; t++) {
        float4 gin0, gin1, gin2, gin3;
        if (kq == 0) {
            const float* gp = g_gin + ((size_t)b0 * 64 + t) * 512 + ug * 4;
            gin0 = *reinterpret_cast<const float4*>(gp);
            gin1 = *reinterpret_cast<const float4*>(gp + 32768);
            gin2 = *reinterpret_cast<const float4*>(gp + 65536);
            gin3 = *reinterpret_cast<const float4*>(gp + 98304);
        }
        ull_t a01[4] = {0, 0, 0, 0}, a23[4] = {0, 0, 0, 0};
        #pragma unroll 8
        for (int j = 0; j < 32; j++) {
            int k = kq * 32 + j;
            uint2 wp = *reinterpret_cast<const uint2*>(&S.whh[k][ug * 2]);
            ull_t h01 = *reinterpret_cast<const ull_t*>(&S.hT[k][0]);
            ull_t h23 = *reinterpret_cast<const ull_t*>(&S.hT[k][2]);
            ull_t d0 = pack2(bf_lo(wp.x), bf_lo(wp.x));
            ull_t d1 = pack2(bf_hi(wp.x), bf_hi(wp.x));
            ull_t d2 = pack2(bf_lo(wp.y), bf_lo(wp.y));
            ull_t d3 = pack2(bf_hi(wp.y), bf_hi(wp.y));
            fma2(a01[0], d0, h01); fma2(a23[0], d0, h23);
            fma2(a01[1], d1, h01); fma2(a23[1], d1, h23);
            fma2(a01[2], d2, h01); fma2(a23[2], d2, h23);
            fma2(a01[3], d3, h01); fma2(a23[3], d3, h23);
        }
        float a[16];
        #pragma unroll
        for (int j = 0; j < 4; j++) {
            float2 f01 = unpk(a01[j]), f23 = unpk(a23[j]);
            a[j] = f01.x; a[4 + j] = f01.y; a[8 + j] = f23.x; a[12 + j] = f23.y;
        }
        if (kq) {
            #pragma unroll
            for (int j = 0; j < 16; j++) S.part[kq - 1][j][ug] = a[j];
        }
        __syncthreads();
        if (kq == 0) {
            #pragma unroll
            for (int j = 0; j < 16; j++)
                a[j] += S.part[0][j][ug] + S.part[1][j][ug] + S.part[2][j][ug];
            float nh0, nh1, nh2, nh3;
            {
                float gi = a[0] + gin0.x, gf = a[1] + gin0.y, gg = a[2] + gin0.z, go = a[3] + gin0.w;
                float cv = sig_fast(gf) * c0 + sig_fast(gi) * tanh_fast(gg);
                c0 = cv; nh0 = sig_fast(go) * tanh_fast(cv);
            }
            {
                float gi = a[4] + gin1.x, gf = a[5] + gin1.y, gg = a[6] + gin1.z, go = a[7] + gin1.w;
                float cv = sig_fast(gf) * c1 + sig_fast(gi) * tanh_fast(gg);
                c1 = cv; nh1 = sig_fast(go) * tanh_fast(cv);
            }
            {
                float gi = a[8] + gin2.x, gf = a[9] + gin2.y, gg = a[10] + gin2.z, go = a[11] + gin2.w;
                float cv = sig_fast(gf) * c2 + sig_fast(gi) * tanh_fast(gg);
                c2 = cv; nh2 = sig_fast(go) * tanh_fast(cv);
            }
            {
                float gi = a[12] + gin3.x, gf = a[13] + gin3.y, gg = a[14] + gin3.z, go = a[15] + gin3.w;
                float cv = sig_fast(gf) * c3 + sig_fast(gi) * tanh_fast(gg);
                c3 = cv; nh3 = sig_fast(go) * tanh_fast(cv);
            }
            *reinterpret_cast<float4*>(S.hT[ug]) = make_float4(nh0, nh1, nh2, nh3);
            g_enc[((size_t)(b0 + 0) * TT + t) * HH + ug] = nh0;
            g_enc[((size_t)(b0 + 1) * TT + t) * HH + ug] = nh1;
            g_enc[((size_t)(b0 + 2) * TT + t) * HH + ug] = nh2;
            g_enc[((size_t)(b0 + 3) * TT + t) * HH + ug] = nh3;
        }
        __syncthreads();
    }
}

// ------------------ enc_proj = input_encoded @ W1e^T + dec_b1 (fp32, f32x2 math) ------------------
__global__ __launch_bounds__(256) void eproj_gemm(const float* __restrict__ W1,
                                                  const float* __restrict__ b1) {
    __shared__ float As[64][68];
    __shared__ float Ws[64][68];
    int m0 = blockIdx.x * 64;
    int n0 = blockIdx.y * 64;
    int tid = threadIdx.x;
    int tx = tid & 15, ty = tid >> 4;
    ull_t acc2[4][2];
    #pragma unroll
    for (int i = 0; i < 4; i++) { acc2[i][0] = 0; acc2[i][1] = 0; }
    for (int kc = 0; kc < 2; kc++) {
        __syncthreads();
        #pragma unroll
        for (int i = 0; i < 16; i++) {
            int idx = tid + i * 256;
            int m = idx >> 6, k = idx & 63;
            As[k][m] = g_enc[(size_t)(m0 + m) * HH + kc * 64 + k];
            Ws[k][m] = W1[(n0 + m) * 384 + 256 + kc * 64 + k];
        }
        __syncthreads();
        #pragma unroll 4
        for (int k = 0; k < 64; k++) {
            float4 a = *reinterpret_cast<const float4*>(&As[k][ty * 4]);
            ull_t w01 = *reinterpret_cast<const ull_t*>(&Ws[k][tx * 4]);
            ull_t w23 = *reinterpret_cast<const ull_t*>(&Ws[k][tx * 4 + 2]);
            ull_t a0 = pack2(a.x, a.x), a1 = pack2(a.y, a.y);
            ull_t a2 = pack2(a.z, a.z), a3 = pack2(a.w, a.w);
            fma2(acc2[0][0], a0, w01); fma2(acc2[0][1], a0, w23);
            fma2(acc2[1][0], a1, w01); fma2(acc2[1][1], a1, w23);
            fma2(acc2[2][0], a2, w01); fma2(acc2[2][1], a2, w23);
            fma2(acc2[3][0], a3, w01); fma2(acc2[3][1], a3, w23);
        }
    }
    #pragma unroll
    for (int i = 0; i < 4; i++) {
        int row = m0 + ty * 4 + i;
        float2 j01 = unpk(acc2[i][0]), j23 = unpk(acc2[i][1]);
        float accv[4] = {j01.x, j01.y, j23.x, j23.y};
        #pragma unroll
        for (int j = 0; j < 4; j++) {
            int n = n0 + tx * 4 + j;
            g_eproj[(size_t)row * HH + n] = accv[j] + b1[n];
        }
    }
}

// ------------------------- persistent decoder: 128 blocks x 4 batches, 64 steps -------------------------
// 512 threads. whh (bf16, 128K) + enc (bf16, 64K) smem-resident.
// Phase G split: warps 0-7 gates GEMM (k-halves), warps 8-15 u GEMM (h-half / c-half).
struct DecSmem {
    unsigned int whh[128][256];   // 128 KB
    unsigned int encB[4][64][64]; // 64 KB  [bb][tt][e/2] bf16x2
    float hcT[256][4];            // 4 KB: rows 0..127 h, 128..255 c
    float partC[16][128];         // 8 KB  gates partials (kh=1)
    float4 partU[128];            // 2 KB  u partials (uh=1)
    float u_s[4][128];
    float ctx_s[4][128];
    float sc[4][64];
    float W2_s[128];
    float fcW_s[128];
    float redy[4][2];
    float xh[4][64];
};

__global__ __launch_bounds__(512) void dec_persist(const float* __restrict__ x,
                                                   const float* __restrict__ dW2,
                                                   const float* __restrict__ fcW,
                                                   const float* __restrict__ fcb,
                                                   const float* __restrict__ fcfW,
                                                   const float* __restrict__ fcfb,
                                                   float* __restrict__ out) {
    extern __shared__ __align__(16) char dec_smem_raw[];
    DecSmem& S = *reinterpret_cast<DecSmem*>(dec_smem_raw);
    int b0 = blockIdx.x * 4;
    int tid = threadIdx.x, lane = tid & 31, wid = tid >> 5;
    int ug = tid & 127;
    float4 wv = make_float4(0.f, 0.f, 0.f, 0.f), bv = wv;
    if (tid < 128) {
        wv = *reinterpret_cast<const float4*>(&g_dWihP[ug * 4]);
        bv = *reinterpret_cast<const float4*>(&g_dbP[ug * 4]);
    }
    // ---- prologue ----
    {
        const uint4* src = reinterpret_cast<const uint4*>(g_WhhB[1]);
        uint4* dst = reinterpret_cast<uint4*>(&S.whh[0][0]);
        for (int i = tid; i < 8192; i += 512) dst[i] = src[i];
    }
    for (int idx = tid; idx < 4 * 64 * 64; idx += 512) {
        int bb = idx >> 12, r = idx & 4095;
        int tt = r >> 6, e2 = r & 63;
        const float* src = g_enc + ((size_t)(b0 + bb) * TT + tt) * HH + 2 * e2;
        S.encB[bb][tt][e2] = pack_bf16x2(src[0], src[1]);
    }
    if (tid < 256) {
        *reinterpret_cast<float4*>(S.hcT[tid]) = make_float4(0.f, 0.f, 0.f, 0.f);
        int bb = tid >> 6, tt = tid & 63;
        S.xh[bb][tt] = x[(size_t)(b0 + bb) * 4096 + tt * 64];
    }
    if (tid < 128) { S.W2_s[tid] = dW2[tid]; S.fcW_s[tid] = fcW[tid]; }
    float fcW128 = fcW[128], fcb0 = fcb[0];
    __syncthreads();

    for (int t = 0; t < 64; t++) {
        // ===== phase G: warps 0-7 gates GEMM, warps 8-15 u GEMM =====
        float a[16];
        ull_t u01 = 0, u23 = 0;
        if (tid < 256) {
            int kh = tid >> 7;   // k-half
            ull_t a01[4] = {0, 0, 0, 0}, a23[4] = {0, 0, 0, 0};
            #pragma unroll 8
            for (int j = 0; j < 64; j++) {
                int k = kh * 64 + j;
                uint2 wp = *reinterpret_cast<const uint2*>(&S.whh[k][ug * 2]);
                ull_t h01 = *reinterpret_cast<const ull_t*>(&S.hcT[k][0]);
                ull_t h23 = *reinterpret_cast<const ull_t*>(&S.hcT[k][2]);
                ull_t d0 = pack2(bf_lo(wp.x), bf_lo(wp.x));
                ull_t d1 = pack2(bf_hi(wp.x), bf_hi(wp.x));
                ull_t d2 = pack2(bf_lo(wp.y), bf_lo(wp.y));
                ull_t d3 = pack2(bf_hi(wp.y), bf_hi(wp.y));
                fma2(a01[0], d0, h01); fma2(a23[0], d0, h23);
                fma2(a01[1], d1, h01); fma2(a23[1], d1, h23);
                fma2(a01[2], d2, h01); fma2(a23[2], d2, h23);
                fma2(a01[3], d3, h01); fma2(a23[3], d3, h23);
            }
            #pragma unroll
            for (int j = 0; j < 4; j++) {
                float2 f01 = unpk(a01[j]), f23 = unpk(a23[j]);
                a[j] = f01.x; a[4 + j] = f01.y; a[8 + j] = f23.x; a[12 + j] = f23.y;
            }
            if (kh) {
                #pragma unroll
                for (int j = 0; j < 16; j++) S.partC[j][ug] = a[j];
            }
        } else {
            int uh = (tid >> 7) & 1;  // 0: W1h over h, 1: W1c over c
            #pragma unroll 8
            for (int j2 = 0; j2 < 64; j2++) {
                int k2 = uh * 64 + j2;
                unsigned int wp = g_W1hcB[k2 * 128 + ug];
                ull_t h0_01 = *reinterpret_cast<const ull_t*>(&S.hcT[2 * k2][0]);
                ull_t h0_23 = *reinterpret_cast<const ull_t*>(&S.hcT[2 * k2][2]);
                ull_t h1_01 = *reinterpret_cast<const ull_t*>(&S.hcT[2 * k2 + 1][0]);
                ull_t h1_23 = *reinterpret_cast<const ull_t*>(&S.hcT[2 * k2 + 1][2]);
                ull_t d0 = pack2(bf_lo(wp), bf_lo(wp));
                ull_t d1 = pack2(bf_hi(wp), bf_hi(wp));
                fma2(u01, d0, h0_01); fma2(u23, d0, h0_23);
                fma2(u01, d1, h1_01); fma2(u23, d1, h1_23);
            }
            if (uh) {
                float2 f0 = unpk(u01), f2 = unpk(u23);
                S.partU[ug] = make_float4(f0.x, f0.y, f2.x, f2.y);
            }
        }
        __syncthreads();
        // combine: tid<128 gates into regs; warps 8-11 combine u into u_s
        if (tid < 128) {
            #pragma unroll
            for (int j = 0; j < 16; j++) a[j] += S.partC[j][ug];
        } else if ((tid >> 7) == 2) {
            float2 f0 = unpk(u01), f2 = unpk(u23);
            float4 p = S.partU[ug];
            S.u_s[0][ug] = f0.x + p.x;
            S.u_s[1][ug] = f0.y + p.y;
            S.u_s[2][ug] = f2.x + p.z;
            S.u_s[3][ug] = f2.y + p.w;
        }
        __syncthreads();
        // ===== phase B1: scores (warp per (batch,t'); eproj fp32 from L2, MLP 8) =====
        #pragma unroll 8
        for (int it = 0; it < 16; it++) {
            int task = it * 16 + wid;
            int bb = task >> 6, tt = task & 63;
            float4 e4 = *reinterpret_cast<const float4*>(
                g_eproj + ((size_t)(b0 + bb) * TT + tt) * HH + lane * 4);
            float4 u4 = *reinterpret_cast<const float4*>(&S.u_s[bb][lane * 4]);
            float4 w4 = *reinterpret_cast<const float4*>(&S.W2_s[lane * 4]);
            float p = w4.x * tanh_fast(e4.x + u4.x) + w4.y * tanh_fast(e4.y + u4.y)
                    + w4.z * tanh_fast(e4.z + u4.z) + w4.w * tanh_fast(e4.w + u4.w);
            #pragma unroll
            for (int o = 16; o; o >>= 1) p += __shfl_xor_sync(0xffffffffu, p, o);
            if (lane == 0) S.sc[bb][tt] = p;
        }
        __syncthreads();
        // ===== phase B2: softmax (warps 4-7, one per batch) =====
        if (wid >= 4 && wid < 8) {
            int bb = wid - 4;
            float s0 = S.sc[bb][lane], s1 = S.sc[bb][lane + 32];
            float m = fmaxf(s0, s1);
            #pragma unroll
            for (int o = 16; o; o >>= 1) m = fmaxf(m, __shfl_xor_sync(0xffffffffu, m, o));
            float e0 = __expf(s0 - m), e1 = __expf(s1 - m);
            float sm = e0 + e1;
            #pragma unroll
            for (int o = 16; o; o >>= 1) sm += __shfl_xor_sync(0xffffffffu, sm, o);
            float inv = 1.0f / sm;
            S.sc[bb][lane] = e0 * inv;
            S.sc[bb][lane + 32] = e1 * inv;
        }
        __syncthreads();
        // ===== phase B3: context + y partials (tid<256; enc bf16 from SMEM) =====
        if (tid < 256) {
            int bb = tid >> 6, e2 = tid & 63;
            float cx0 = 0.f, cx1 = 0.f;
            #pragma unroll 8
            for (int tt = 0; tt < 64; tt++) {
                float2 f = unpack_bf16x2(S.encB[bb][tt][e2]);
                float av = S.sc[bb][tt];
                cx0 = fmaf(av, f.x, cx0);
                cx1 = fmaf(av, f.y, cx1);
            }
            S.ctx_s[bb][2 * e2] = cx0;
            S.ctx_s[bb][2 * e2 + 1] = cx1;
            float p = cx0 * S.fcW_s[2 * e2] + cx1 * S.fcW_s[2 * e2 + 1];
            #pragma unroll
            for (int o = 16; o; o >>= 1) p += __shfl_xor_sync(0xffffffffu, p, o);
            if (lane == 0) S.redy[bb][(tid >> 5) & 1] = p;
        }
        __syncthreads();
        // ===== epilogue: LSTM cells (tid<128; a[16] in registers) =====
        if (tid < 128) {
            float yv[4];
            #pragma unroll
            for (int b = 0; b < 4; b++)
                yv[b] = S.redy[b][0] + S.redy[b][1] + S.xh[b][t] * fcW128 + fcb0;
            float4 co = *reinterpret_cast<const float4*>(S.hcT[128 + ug]);
            float cvals[4] = {co.x, co.y, co.z, co.w};
            float nh[4], nc[4];
            #pragma unroll
            for (int b = 0; b < 4; b++) {
                float y = yv[b];
                float gi = a[b * 4 + 0] + y * wv.x + bv.x;
                float gf = a[b * 4 + 1] + y * wv.y + bv.y;
                float gg = a[b * 4 + 2] + y * wv.z + bv.z;
                float go = a[b * 4 + 3] + y * wv.w + bv.w;
                float cv = sig_fast(gf) * cvals[b] + sig_fast(gi) * tanh_fast(gg);
                nc[b] = cv;
                nh[b] = sig_fast(go) * tanh_fast(cv);
            }
            *reinterpret_cast<float4*>(S.hcT[128 + ug]) = make_float4(nc[0], nc[1], nc[2], nc[3]);
            *reinterpret_cast<float4*>(S.hcT[ug]) = make_float4(nh[0], nh[1], nh[2], nh[3]);
        }
        __syncthreads();
    }

    // ---- final: out[b] = [h, ctx] @ fcf_W^T + fcf_b ----
    if (tid < 128) {
        int bb = wid;  // 0..3
        float p = 0.f;
        #pragma unroll
        for (int q = 0; q < 4; q++) {
            int e = lane + 32 * q;
            p += S.hcT[e][bb] * fcfW[e] + S.ctx_s[bb][e] * fcfW[128 + e];
        }
        #pragma unroll
        for (int o = 16; o; o >>= 1) p += __shfl_xor_sync(0xffffffffu, p, o);
        if (lane == 0) out[b0 + bb] = p + fcfb[0];
    }
}

// ------------------------- launch -------------------------
extern "C" void kernel_launch(void* const* d_in, const int* in_sizes, int n_in,
                              void* d_out, int out_size) {
    const float* x        = (const float*)d_in[0];
    const float* attnW    = (const float*)d_in[1];
    const float* attnB    = (const float*)d_in[2];
    const float* enc_Wih  = (const float*)d_in[3];
    const float* enc_Whh  = (const float*)d_in[4];
    const float* enc_bih  = (const float*)d_in[5];
    const float* enc_bhh  = (const float*)d_in[6];
    const float* dec_W1   = (const float*)d_in[7];
    const float* dec_b1   = (const float*)d_in[8];
    const float* dec_W2   = (const float*)d_in[9];
    // d_in[10] = dec_b2 (cancels in softmax)
    const float* dec_Wih  = (const float*)d_in[11];
    const float* dec_Whh  = (const float*)d_in[12];
    const float* dec_bih  = (const float*)d_in[13];
    const float* dec_bhh  = (const float*)d_in[14];
    const float* fc_W     = (const float*)d_in[15];
    const float* fc_b     = (const float*)d_in[16];
    const float* fcf_W    = (const float*)d_in[17];
    const float* fcf_b    = (const float*)d_in[18];
    float* out = (float*)d_out;

    int enc_smem = (int)sizeof(EncSmem);
    int dec_smem = (int)sizeof(DecSmem);
    cudaFuncSetAttribute(enc_persist, cudaFuncAttributeMaxDynamicSharedMemorySize, enc_smem);
    cudaFuncSetAttribute(dec_persist, cudaFuncAttributeMaxDynamicSharedMemorySize, dec_smem);

    prep_weights<<<195, 256>>>(enc_Whh, dec_Whh, dec_Wih, dec_bih, dec_bhh, dec_W1);
    prep_attn<<<BB, 64>>>(x, attnW, attnB);
    gin_gemm<<<dim3(BB, 8), 256>>>(x, enc_Wih, enc_bih, enc_bhh);
    enc_persist<<<128, 512, enc_smem>>>();
    eproj_gemm<<<dim3(512, 2), 256>>>(dec_W1, dec_b1);
    dec_persist<<<128, 512, dec_smem>>>(x, dec_W2, fc_W, fc_b, fcf_W, fcf_b, out);
}

// round 15
// speedup vs baseline: 1.2688x; 1.0024x over previous
#include <cuda_runtime.h>
#include <cuda_bf16.h>
#include <math.h>

#define BB 512
#define TT 64
#define NINx 63
#define HH 128

typedef unsigned long long ull_t;

// ------------------------- device scratch (static) -------------------------
__device__ float g_attn[BB * 64];
__device__ float g_gin[(size_t)BB * TT * 512];    // permuted gate order, biases folded
__device__ float g_enc[(size_t)BB * TT * HH];     // input_encoded [b][t][e] fp32
__device__ float g_eproj[(size_t)BB * TT * HH];   // enc_proj (+dec_b1) fp32
__device__ unsigned int g_WhhB[2][128 * 256];     // [enc/dec][k][g/2] bf16x2, permuted
__device__ unsigned int g_W1hcB[128 * 128];       // [k2][e] bf16x2 of (W1h;W1c)^T pairs
__device__ float g_dWihP[512], g_dbP[512];        // permuted dec input weights/biases

__device__ __forceinline__ float tanh_fast(float v) {
    float r; asm("tanh.approx.f32 %0, %1;" : "=f"(r) : "f"(v)); return r;
}
__device__ __forceinline__ float sig_fast(float v) {
    return 0.5f * tanh_fast(0.5f * v) + 0.5f;
}
__device__ __forceinline__ unsigned int pack_bf16x2(float a, float b) {
    __nv_bfloat162 p = __floats2bfloat162_rn(a, b);
    return *reinterpret_cast<unsigned int*>(&p);
}
__device__ __forceinline__ float2 unpack_bf16x2(unsigned int u) {
    return __bfloat1622float2(*reinterpret_cast<__nv_bfloat162*>(&u));
}
// ---- packed f32x2 helpers (Blackwell) ----
__device__ __forceinline__ ull_t pack2(float lo, float hi) {
    ull_t r; asm("mov.b64 %0, {%1, %2};" : "=l"(r) : "f"(lo), "f"(hi)); return r;
}
__device__ __forceinline__ float2 unpk(ull_t v) {
    float2 f; asm("mov.b64 {%0, %1}, %2;" : "=f"(f.x), "=f"(f.y) : "l"(v)); return f;
}
__device__ __forceinline__ void fma2(ull_t& d, ull_t a, ull_t b) {
    asm("fma.rn.f32x2 %0, %1, %2, %0;" : "+l"(d) : "l"(a), "l"(b));
}
__device__ __forceinline__ float bf_lo(unsigned int u) { return __uint_as_float(u << 16); }
__device__ __forceinline__ float bf_hi(unsigned int u) { return __uint_as_float(u & 0xFFFF0000u); }

// ------------------------- weight prep (permute + transpose + bf16) -------------------------
__global__ void prep_weights(const float* __restrict__ eWhh,
                             const float* __restrict__ dWhh,
                             const float* __restrict__ dWih,
                             const float* __restrict__ dbih,
                             const float* __restrict__ dbhh,
                             const float* __restrict__ dW1) {
    int i = blockIdx.x * 256 + threadIdx.x;
    if (i < 32768) {
        int k = i >> 8, g2 = i & 255;
        int gp0 = 2 * g2, gp1 = 2 * g2 + 1;
        int o0 = (gp0 & 3) * HH + (gp0 >> 2);
        int o1 = (gp1 & 3) * HH + (gp1 >> 2);
        g_WhhB[0][k * 256 + g2] = pack_bf16x2(eWhh[o0 * HH + k], eWhh[o1 * HH + k]);
        g_WhhB[1][k * 256 + g2] = pack_bf16x2(dWhh[o0 * HH + k], dWhh[o1 * HH + k]);
    } else if (i < 33280) {
        int gp = i - 32768;
        int orig = (gp & 3) * HH + (gp >> 2);
        g_dWihP[gp] = dWih[orig];
        g_dbP[gp] = dbih[orig] + dbhh[orig];
    } else if (i < 33280 + 16384) {
        int j = i - 33280;
        int e = j & 127, k2 = j >> 7;   // k2 0..127 covers k 0..255 (W1h then W1c)
        g_W1hcB[k2 * 128 + e] = pack_bf16x2(dW1[e * 384 + 2 * k2],
                                            dW1[e * 384 + 2 * k2 + 1]);
    }
}

// ------------------------- encoder attention (time- & state-invariant) -------------------------
__global__ void prep_attn(const float* __restrict__ x,
                          const float* __restrict__ attnW,
                          const float* __restrict__ attnB) {
    __shared__ float s_s[64];
    __shared__ float red[2];
    int b = blockIdx.x, n = threadIdx.x;
    float s = -1e30f;
    if (n < NINx) {
        float acc = attnB[0];
        const float* wt = attnW + 2 * HH;
        #pragma unroll 8
        for (int t = 0; t < TT; t++) acc = fmaf(x[b * 4096 + t * 64 + n + 1], wt[t], acc);
        s = acc;
    }
    s_s[n] = s;
    __syncthreads();
    if (n < 32) {
        float m = fmaxf(s_s[n], s_s[n + 32]);
        #pragma unroll
        for (int o = 16; o; o >>= 1) m = fmaxf(m, __shfl_xor_sync(0xffffffffu, m, o));
        if (n == 0) red[0] = m;
    }
    __syncthreads();
    float e = (n < NINx) ? expf(s - red[0]) : 0.f;
    s_s[n] = e;
    __syncthreads();
    if (n < 32) {
        float sm = s_s[n] + s_s[n + 32];
        #pragma unroll
        for (int o = 16; o; o >>= 1) sm += __shfl_xor_sync(0xffffffffu, sm, o);
        if (n == 0) red[1] = sm;
    }
    __syncthreads();
    if (n < 64) g_attn[b * 64 + n] = (n < NINx) ? e / red[1] : 0.f;
}

// ------------- gin[b,t,g'] = sum_n attn[b,n]*x[b,t,n+1]*Wih[orig(g'),n] + bias -------------
__global__ __launch_bounds__(256) void gin_gemm(const float* __restrict__ x,
                                                const float* __restrict__ Wih,
                                                const float* __restrict__ bih,
                                                const float* __restrict__ bhh) {
    __shared__ float attn_s[64];
    __shared__ float As[64][68];
    __shared__ float Ws[64][68];
    int bb = blockIdx.x;
    int g0 = blockIdx.y * 64;
    int tid = threadIdx.x;
    if (tid < 64) attn_s[tid] = g_attn[bb * 64 + tid];
    __syncthreads();
    #pragma unroll
    for (int i = 0; i < 16; i++) {
        int idx = tid + i * 256;
        int m = idx >> 6, k = idx & 63;
        As[k][m] = (k < NINx) ? attn_s[k] * x[bb * 4096 + m * 64 + k + 1] : 0.f;
        int gp = g0 + m;
        int orig = (gp & 3) * HH + (gp >> 2);
        Ws[k][m] = (k < NINx) ? Wih[orig * NINx + k] : 0.f;
    }
    __syncthreads();
    int tx = tid & 15, ty = tid >> 4;
    ull_t acc2[4][2];
    #pragma unroll
    for (int i = 0; i < 4; i++) { acc2[i][0] = 0; acc2[i][1] = 0; }
    #pragma unroll 4
    for (int k = 0; k < 64; k++) {
        float4 a = *reinterpret_cast<const float4*>(&As[k][ty * 4]);
        ull_t w01 = *reinterpret_cast<const ull_t*>(&Ws[k][tx * 4]);
        ull_t w23 = *reinterpret_cast<const ull_t*>(&Ws[k][tx * 4 + 2]);
        ull_t a0 = pack2(a.x, a.x), a1 = pack2(a.y, a.y);
        ull_t a2 = pack2(a.z, a.z), a3 = pack2(a.w, a.w);
        fma2(acc2[0][0], a0, w01); fma2(acc2[0][1], a0, w23);
        fma2(acc2[1][0], a1, w01); fma2(acc2[1][1], a1, w23);
        fma2(acc2[2][0], a2, w01); fma2(acc2[2][1], a2, w23);
        fma2(acc2[3][0], a3, w01); fma2(acc2[3][1], a3, w23);
    }
    #pragma unroll
    for (int i = 0; i < 4; i++) {
        int t = ty * 4 + i;
        float2 j01 = unpk(acc2[i][0]), j23 = unpk(acc2[i][1]);
        float accv[4] = {j01.x, j01.y, j23.x, j23.y};
        #pragma unroll
        for (int j = 0; j < 4; j++) {
            int gp = g0 + tx * 4 + j;
            int orig = (gp & 3) * HH + (gp >> 2);
            g_gin[((size_t)bb * TT + t) * 512 + gp] = accv[j] + bih[orig] + bhh[orig];
        }
    }
}

// ------------------------- persistent encoder: 128 blocks x 4 batches, 64 steps -------------------------
struct EncSmem {
    unsigned int whh[128][256];   // bf16x2 [k][g/2]   128 KB
    float hT[128][4];             // [unit][batch]
    float part[3][16][128];       // partials from kq=1..3
};

__global__ __launch_bounds__(512) void enc_persist() {
    extern __shared__ __align__(16) char enc_smem_raw[];
    EncSmem& S = *reinterpret_cast<EncSmem*>(enc_smem_raw);
    int b0 = blockIdx.x * 4;
    int tid = threadIdx.x;
    int ug = tid & 127, kq = tid >> 7;
    {
        const uint4* src = reinterpret_cast<const uint4*>(g_WhhB[0]);
        uint4* dst = reinterpret_cast<uint4*>(&S.whh[0][0]);
        for (int i = tid; i < 8192; i += 512) dst[i] = src[i];
    }
    if (tid < 128) *reinterpret_cast<float4*>(S.hT[tid]) = make_float4(0.f, 0.f, 0.f, 0.f);
    float c0 = 0.f, c1 = 0.f, c2 = 0.f, c3 = 0.f;
    __syncthreads();
    for (int t = 0; t < 64; t++) {
        float4 gin0, gin1, gin2, gin3;
        if (kq == 0) {
            const float* gp = g_gin + ((size_t)b0 * 64 + t) * 512 + ug * 4;
            gin0 = *reinterpret_cast<const float4*>(gp);
            gin1 = *reinterpret_cast<const float4*>(gp + 32768);
            gin2 = *reinterpret_cast<const float4*>(gp + 65536);
            gin3 = *reinterpret_cast<const float4*>(gp + 98304);
        }
        ull_t a01[4] = {0, 0, 0, 0}, a23[4] = {0, 0, 0, 0};
        #pragma unroll 8
        for (int j = 0; j < 32; j++) {
            int k = kq * 32 + j;
            uint2 wp = *reinterpret_cast<const uint2*>(&S.whh[k][ug * 2]);
            ull_t h01 = *reinterpret_cast<const ull_t*>(&S.hT[k][0]);
            ull_t h23 = *reinterpret_cast<const ull_t*>(&S.hT[k][2]);
            ull_t d0 = pack2(bf_lo(wp.x), bf_lo(wp.x));
            ull_t d1 = pack2(bf_hi(wp.x), bf_hi(wp.x));
            ull_t d2 = pack2(bf_lo(wp.y), bf_lo(wp.y));
            ull_t d3 = pack2(bf_hi(wp.y), bf_hi(wp.y));
            fma2(a01[0], d0, h01); fma2(a23[0], d0, h23);
            fma2(a01[1], d1, h01); fma2(a23[1], d1, h23);
            fma2(a01[2], d2, h01); fma2(a23[2], d2, h23);
            fma2(a01[3], d3, h01); fma2(a23[3], d3, h23);
        }
        float a[16];
        #pragma unroll
        for (int j = 0; j < 4; j++) {
            float2 f01 = unpk(a01[j]), f23 = unpk(a23[j]);
            a[j] = f01.x; a[4 + j] = f01.y; a[8 + j] = f23.x; a[12 + j] = f23.y;
        }
        if (kq) {
            #pragma unroll
            for (int j = 0; j < 16; j++) S.part[kq - 1][j][ug] = a[j];
        }
        __syncthreads();
        if (kq == 0) {
            #pragma unroll
            for (int j = 0; j < 16; j++)
                a[j] += S.part[0][j][ug] + S.part[1][j][ug] + S.part[2][j][ug];
            float nh0, nh1, nh2, nh3;
            {
                float gi = a[0] + gin0.x, gf = a[1] + gin0.y, gg = a[2] + gin0.z, go = a[3] + gin0.w;
                float cv = sig_fast(gf) * c0 + sig_fast(gi) * tanh_fast(gg);
                c0 = cv; nh0 = sig_fast(go) * tanh_fast(cv);
            }
            {
                float gi = a[4] + gin1.x, gf = a[5] + gin1.y, gg = a[6] + gin1.z, go = a[7] + gin1.w;
                float cv = sig_fast(gf) * c1 + sig_fast(gi) * tanh_fast(gg);
                c1 = cv; nh1 = sig_fast(go) * tanh_fast(cv);
            }
            {
                float gi = a[8] + gin2.x, gf = a[9] + gin2.y, gg = a[10] + gin2.z, go = a[11] + gin2.w;
                float cv = sig_fast(gf) * c2 + sig_fast(gi) * tanh_fast(gg);
                c2 = cv; nh2 = sig_fast(go) * tanh_fast(cv);
            }
            {
                float gi = a[12] + gin3.x, gf = a[13] + gin3.y, gg = a[14] + gin3.z, go = a[15] + gin3.w;
                float cv = sig_fast(gf) * c3 + sig_fast(gi) * tanh_fast(gg);
                c3 = cv; nh3 = sig_fast(go) * tanh_fast(cv);
            }
            *reinterpret_cast<float4*>(S.hT[ug]) = make_float4(nh0, nh1, nh2, nh3);
            g_enc[((size_t)(b0 + 0) * TT + t) * HH + ug] = nh0;
            g_enc[((size_t)(b0 + 1) * TT + t) * HH + ug] = nh1;
            g_enc[((size_t)(b0 + 2) * TT + t) * HH + ug] = nh2;
            g_enc[((size_t)(b0 + 3) * TT + t) * HH + ug] = nh3;
        }
        __syncthreads();
    }
}

// ------------------ enc_proj = input_encoded @ W1e^T + dec_b1 (fp32, f32x2 math) ------------------
__global__ __launch_bounds__(256) void eproj_gemm(const float* __restrict__ W1,
                                                  const float* __restrict__ b1) {
    __shared__ float As[64][68];
    __shared__ float Ws[64][68];
    int m0 = blockIdx.x * 64;
    int n0 = blockIdx.y * 64;
    int tid = threadIdx.x;
    int tx = tid & 15, ty = tid >> 4;
    ull_t acc2[4][2];
    #pragma unroll
    for (int i = 0; i < 4; i++) { acc2[i][0] = 0; acc2[i][1] = 0; }
    for (int kc = 0; kc < 2; kc++) {
        __syncthreads();
        #pragma unroll
        for (int i = 0; i < 16; i++) {
            int idx = tid + i * 256;
            int m = idx >> 6, k = idx & 63;
            As[k][m] = g_enc[(size_t)(m0 + m) * HH + kc * 64 + k];
            Ws[k][m] = W1[(n0 + m) * 384 + 256 + kc * 64 + k];
        }
        __syncthreads();
        #pragma unroll 4
        for (int k = 0; k < 64; k++) {
            float4 a = *reinterpret_cast<const float4*>(&As[k][ty * 4]);
            ull_t w01 = *reinterpret_cast<const ull_t*>(&Ws[k][tx * 4]);
            ull_t w23 = *reinterpret_cast<const ull_t*>(&Ws[k][tx * 4 + 2]);
            ull_t a0 = pack2(a.x, a.x), a1 = pack2(a.y, a.y);
            ull_t a2 = pack2(a.z, a.z), a3 = pack2(a.w, a.w);
            fma2(acc2[0][0], a0, w01); fma2(acc2[0][1], a0, w23);
            fma2(acc2[1][0], a1, w01); fma2(acc2[1][1], a1, w23);
            fma2(acc2[2][0], a2, w01); fma2(acc2[2][1], a2, w23);
            fma2(acc2[3][0], a3, w01); fma2(acc2[3][1], a3, w23);
        }
    }
    #pragma unroll
    for (int i = 0; i < 4; i++) {
        int row = m0 + ty * 4 + i;
        float2 j01 = unpk(acc2[i][0]), j23 = unpk(acc2[i][1]);
        float accv[4] = {j01.x, j01.y, j23.x, j23.y};
        #pragma unroll
        for (int j = 0; j < 4; j++) {
            int n = n0 + tx * 4 + j;
            g_eproj[(size_t)row * HH + n] = accv[j] + b1[n];
        }
    }
}

// ------------------------- persistent decoder: 128 blocks x 4 batches, 64 steps -------------------------
// 512 threads. whh (bf16, 128K) + enc (bf16, 64K) smem-resident.
// Phase G split: warps 0-7 gates GEMM (k-halves), warps 8-15 u GEMM (h-half / c-half).
struct DecSmem {
    unsigned int whh[128][256];   // 128 KB
    unsigned int encB[4][64][64]; // 64 KB  [bb][tt][e/2] bf16x2
    float hcT[256][4];            // 4 KB: rows 0..127 h, 128..255 c
    float partC[16][128];         // 8 KB  gates partials (kh=1)
    float4 partU[128];            // 2 KB  u partials (uh=1)
    float u_s[4][128];
    float ctx_s[4][128];
    float sc[4][64];
    float W2_s[128];
    float fcW_s[128];
    float redy[4][2];
    float xh[4][64];
};

__global__ __launch_bounds__(512) void dec_persist(const float* __restrict__ x,
                                                   const float* __restrict__ dW2,
                                                   const float* __restrict__ fcW,
                                                   const float* __restrict__ fcb,
                                                   const float* __restrict__ fcfW,
                                                   const float* __restrict__ fcfb,
                                                   float* __restrict__ out) {
    extern __shared__ __align__(16) char dec_smem_raw[];
    DecSmem& S = *reinterpret_cast<DecSmem*>(dec_smem_raw);
    int b0 = blockIdx.x * 4;
    int tid = threadIdx.x, lane = tid & 31, wid = tid >> 5;
    int ug = tid & 127;
    float4 wv = make_float4(0.f, 0.f, 0.f, 0.f), bv = wv;
    if (tid < 128) {
        wv = *reinterpret_cast<const float4*>(&g_dWihP[ug * 4]);
        bv = *reinterpret_cast<const float4*>(&g_dbP[ug * 4]);
    }
    // ---- prologue ----
    {
        const uint4* src = reinterpret_cast<const uint4*>(g_WhhB[1]);
        uint4* dst = reinterpret_cast<uint4*>(&S.whh[0][0]);
        for (int i = tid; i < 8192; i += 512) dst[i] = src[i];
    }
    for (int idx = tid; idx < 4 * 64 * 64; idx += 512) {
        int bb = idx >> 12, r = idx & 4095;
        int tt = r >> 6, e2 = r & 63;
        const float* src = g_enc + ((size_t)(b0 + bb) * TT + tt) * HH + 2 * e2;
        S.encB[bb][tt][e2] = pack_bf16x2(src[0], src[1]);
    }
    if (tid < 256) {
        *reinterpret_cast<float4*>(S.hcT[tid]) = make_float4(0.f, 0.f, 0.f, 0.f);
        int bb = tid >> 6, tt = tid & 63;
        S.xh[bb][tt] = x[(size_t)(b0 + bb) * 4096 + tt * 64];
    }
    if (tid < 128) { S.W2_s[tid] = dW2[tid]; S.fcW_s[tid] = fcW[tid]; }
    float fcW128 = fcW[128], fcb0 = fcb[0];
    __syncthreads();

    for (int t = 0; t < 64; t++) {
        // ===== phase G: warps 0-7 gates GEMM, warps 8-15 u GEMM =====
        float a[16];
        ull_t u01 = 0, u23 = 0;
        if (tid < 256) {
            int kh = tid >> 7;   // k-half
            ull_t a01[4] = {0, 0, 0, 0}, a23[4] = {0, 0, 0, 0};
            #pragma unroll 8
            for (int j = 0; j < 64; j++) {
                int k = kh * 64 + j;
                uint2 wp = *reinterpret_cast<const uint2*>(&S.whh[k][ug * 2]);
                ull_t h01 = *reinterpret_cast<const ull_t*>(&S.hcT[k][0]);
                ull_t h23 = *reinterpret_cast<const ull_t*>(&S.hcT[k][2]);
                ull_t d0 = pack2(bf_lo(wp.x), bf_lo(wp.x));
                ull_t d1 = pack2(bf_hi(wp.x), bf_hi(wp.x));
                ull_t d2 = pack2(bf_lo(wp.y), bf_lo(wp.y));
                ull_t d3 = pack2(bf_hi(wp.y), bf_hi(wp.y));
                fma2(a01[0], d0, h01); fma2(a23[0], d0, h23);
                fma2(a01[1], d1, h01); fma2(a23[1], d1, h23);
                fma2(a01[2], d2, h01); fma2(a23[2], d2, h23);
                fma2(a01[3], d3, h01); fma2(a23[3], d3, h23);
            }
            #pragma unroll
            for (int j = 0; j < 4; j++) {
                float2 f01 = unpk(a01[j]), f23 = unpk(a23[j]);
                a[j] = f01.x; a[4 + j] = f01.y; a[8 + j] = f23.x; a[12 + j] = f23.y;
            }
            if (kh) {
                #pragma unroll
                for (int j = 0; j < 16; j++) S.partC[j][ug] = a[j];
            }
        } else {
            int uh = (tid >> 7) & 1;  // 0: W1h over h, 1: W1c over c
            #pragma unroll 8
            for (int j2 = 0; j2 < 64; j2++) {
                int k2 = uh * 64 + j2;
                unsigned int wp = g_W1hcB[k2 * 128 + ug];
                ull_t h0_01 = *reinterpret_cast<const ull_t*>(&S.hcT[2 * k2][0]);
                ull_t h0_23 = *reinterpret_cast<const ull_t*>(&S.hcT[2 * k2][2]);
                ull_t h1_01 = *reinterpret_cast<const ull_t*>(&S.hcT[2 * k2 + 1][0]);
                ull_t h1_23 = *reinterpret_cast<const ull_t*>(&S.hcT[2 * k2 + 1][2]);
                ull_t d0 = pack2(bf_lo(wp), bf_lo(wp));
                ull_t d1 = pack2(bf_hi(wp), bf_hi(wp));
                fma2(u01, d0, h0_01); fma2(u23, d0, h0_23);
                fma2(u01, d1, h1_01); fma2(u23, d1, h1_23);
            }
            if (uh) {
                float2 f0 = unpk(u01), f2 = unpk(u23);
                S.partU[ug] = make_float4(f0.x, f0.y, f2.x, f2.y);
            }
        }
        __syncthreads();
        // combine: tid<128 gates into regs; warps 8-11 combine u into u_s
        if (tid < 128) {
            #pragma unroll
            for (int j = 0; j < 16; j++) a[j] += S.partC[j][ug];
        } else if ((tid >> 7) == 2) {
            float2 f0 = unpk(u01), f2 = unpk(u23);
            float4 p = S.partU[ug];
            S.u_s[0][ug] = f0.x + p.x;
            S.u_s[1][ug] = f0.y + p.y;
            S.u_s[2][ug] = f2.x + p.z;
            S.u_s[3][ug] = f2.y + p.w;
        }
        __syncthreads();
        // ===== phase B1: scores (warp per (batch,t'); eproj fp32 from L2, MLP 8) =====
        #pragma unroll 8
        for (int it = 0; it < 16; it++) {
            int task = it * 16 + wid;
            int bb = task >> 6, tt = task & 63;
            float4 e4 = *reinterpret_cast<const float4*>(
                g_eproj + ((size_t)(b0 + bb) * TT + tt) * HH + lane * 4);
            float4 u4 = *reinterpret_cast<const float4*>(&S.u_s[bb][lane * 4]);
            float4 w4 = *reinterpret_cast<const float4*>(&S.W2_s[lane * 4]);
            float p = w4.x * tanh_fast(e4.x + u4.x) + w4.y * tanh_fast(e4.y + u4.y)
                    + w4.z * tanh_fast(e4.z + u4.z) + w4.w * tanh_fast(e4.w + u4.w);
            #pragma unroll
            for (int o = 16; o; o >>= 1) p += __shfl_xor_sync(0xffffffffu, p, o);
            if (lane == 0) S.sc[bb][tt] = p;
        }
        __syncthreads();
        // ===== phase B2: softmax (warps 4-7, one per batch) =====
        if (wid >= 4 && wid < 8) {
            int bb = wid - 4;
            float s0 = S.sc[bb][lane], s1 = S.sc[bb][lane + 32];
            float m = fmaxf(s0, s1);
            #pragma unroll
            for (int o = 16; o; o >>= 1) m = fmaxf(m, __shfl_xor_sync(0xffffffffu, m, o));
            float e0 = __expf(s0 - m), e1 = __expf(s1 - m);
            float sm = e0 + e1;
            #pragma unroll
            for (int o = 16; o; o >>= 1) sm += __shfl_xor_sync(0xffffffffu, sm, o);
            float inv = 1.0f / sm;
            S.sc[bb][lane] = e0 * inv;
            S.sc[bb][lane + 32] = e1 * inv;
        }
        __syncthreads();
        // ===== phase B3: context + y partials (tid<256; enc bf16 from SMEM) =====
        if (tid < 256) {
            int bb = tid >> 6, e2 = tid & 63;
            float cx0 = 0.f, cx1 = 0.f;
            #pragma unroll 8
            for (int tt = 0; tt < 64; tt++) {
                float2 f = unpack_bf16x2(S.encB[bb][tt][e2]);
                float av = S.sc[bb][tt];
                cx0 = fmaf(av, f.x, cx0);
                cx1 = fmaf(av, f.y, cx1);
            }
            S.ctx_s[bb][2 * e2] = cx0;
            S.ctx_s[bb][2 * e2 + 1] = cx1;
            float p = cx0 * S.fcW_s[2 * e2] + cx1 * S.fcW_s[2 * e2 + 1];
            #pragma unroll
            for (int o = 16; o; o >>= 1) p += __shfl_xor_sync(0xffffffffu, p, o);
            if (lane == 0) S.redy[bb][(tid >> 5) & 1] = p;
        }
        __syncthreads();
        // ===== epilogue: LSTM cells (tid<128; a[16] in registers) =====
        if (tid < 128) {
            float yv[4];
            #pragma unroll
            for (int b = 0; b < 4; b++)
                yv[b] = S.redy[b][0] + S.redy[b][1] + S.xh[b][t] * fcW128 + fcb0;
            float4 co = *reinterpret_cast<const float4*>(S.hcT[128 + ug]);
            float cvals[4] = {co.x, co.y, co.z, co.w};
            float nh[4], nc[4];
            #pragma unroll
            for (int b = 0; b < 4; b++) {
                float y = yv[b];
                float gi = a[b * 4 + 0] + y * wv.x + bv.x;
                float gf = a[b * 4 + 1] + y * wv.y + bv.y;
                float gg = a[b * 4 + 2] + y * wv.z + bv.z;
                float go = a[b * 4 + 3] + y * wv.w + bv.w;
                float cv = sig_fast(gf) * cvals[b] + sig_fast(gi) * tanh_fast(gg);
                nc[b] = cv;
                nh[b] = sig_fast(go) * tanh_fast(cv);
            }
            *reinterpret_cast<float4*>(S.hcT[128 + ug]) = make_float4(nc[0], nc[1], nc[2], nc[3]);
            *reinterpret_cast<float4*>(S.hcT[ug]) = make_float4(nh[0], nh[1], nh[2], nh[3]);
        }
        __syncthreads();
    }

    // ---- final: out[b] = [h, ctx] @ fcf_W^T + fcf_b ----
    if (tid < 128) {
        int bb = wid;  // 0..3
        float p = 0.f;
        #pragma unroll
        for (int q = 0; q < 4; q++) {
            int e = lane + 32 * q;
            p += S.hcT[e][bb] * fcfW[e] + S.ctx_s[bb][e] * fcfW[128 + e];
        }
        #pragma unroll
        for (int o = 16; o; o >>= 1) p += __shfl_xor_sync(0xffffffffu, p, o);
        if (lane == 0) out[b0 + bb] = p + fcfb[0];
    }
}

// ------------------------- launch -------------------------
extern "C" void kernel_launch(void* const* d_in, const int* in_sizes, int n_in,
                              void* d_out, int out_size) {
    const float* x        = (const float*)d_in[0];
    const float* attnW    = (const float*)d_in[1];
    const float* attnB    = (const float*)d_in[2];
    const float* enc_Wih  = (const float*)d_in[3];
    const float* enc_Whh  = (const float*)d_in[4];
    const float* enc_bih  = (const float*)d_in[5];
    const float* enc_bhh  = (const float*)d_in[6];
    const float* dec_W1   = (const float*)d_in[7];
    const float* dec_b1   = (const float*)d_in[8];
    const float* dec_W2   = (const float*)d_in[9];
    // d_in[10] = dec_b2 (cancels in softmax)
    const float* dec_Wih  = (const float*)d_in[11];
    const float* dec_Whh  = (const float*)d_in[12];
    const float* dec_bih  = (const float*)d_in[13];
    const float* dec_bhh  = (const float*)d_in[14];
    const float* fc_W     = (const float*)d_in[15];
    const float* fc_b     = (const float*)d_in[16];
    const float* fcf_W    = (const float*)d_in[17];
    const float* fcf_b    = (const float*)d_in[18];
    float* out = (float*)d_out;

    int enc_smem = (int)sizeof(EncSmem);
    int dec_smem = (int)sizeof(DecSmem);
    cudaFuncSetAttribute(enc_persist, cudaFuncAttributeMaxDynamicSharedMemorySize, enc_smem);
    cudaFuncSetAttribute(dec_persist, cudaFuncAttributeMaxDynamicSharedMemorySize, dec_smem);

    prep_weights<<<195, 256>>>(enc_Whh, dec_Whh, dec_Wih, dec_bih, dec_bhh, dec_W1);
    prep_attn<<<BB, 64>>>(x, attnW, attnB);
    gin_gemm<<<dim3(BB, 8), 256>>>(x, enc_Wih, enc_bih, enc_bhh);
    enc_persist<<<128, 512, enc_smem>>>();
    eproj_gemm<<<dim3(512, 2), 256>>>(dec_W1, dec_b1);
    dec_persist<<<128, 512, dec_smem>>>(x, dec_W2, fc_W, fc_b, fcf_W, fcf_b, out);
}

// round 16
// speedup vs baseline: 1.2696x; 1.0006x over previous
#include <cuda_runtime.h>
#include <cuda_bf16.h>
#include <math.h>

#define BB 512
#define TT 64
#define NINx 63
#define HH 128

typedef unsigned long long ull_t;

// ------------------------- device scratch (static) -------------------------
__device__ float g_attn[BB * 64];
__device__ float g_gin[(size_t)BB * TT * 512];    // permuted gate order, biases folded
__device__ float g_enc[(size_t)BB * TT * HH];     // input_encoded [b][t][e] fp32
__device__ float g_eproj[(size_t)BB * TT * HH];   // enc_proj (+dec_b1) fp32
__device__ unsigned int g_WhhB[2][128 * 256];     // [enc/dec][k][g/2] bf16x2, permuted
__device__ unsigned int g_W1hcB[128 * 128];       // [k2][e] bf16x2 of (W1h;W1c)^T pairs
__device__ float g_dWihP[512], g_dbP[512];        // permuted dec input weights/biases

__device__ __forceinline__ float tanh_fast(float v) {
    float r; asm("tanh.approx.f32 %0, %1;" : "=f"(r) : "f"(v)); return r;
}
__device__ __forceinline__ float sig_fast(float v) {
    return 0.5f * tanh_fast(0.5f * v) + 0.5f;
}
__device__ __forceinline__ unsigned int pack_bf16x2(float a, float b) {
    __nv_bfloat162 p = __floats2bfloat162_rn(a, b);
    return *reinterpret_cast<unsigned int*>(&p);
}
__device__ __forceinline__ float2 unpack_bf16x2(unsigned int u) {
    return __bfloat1622float2(*reinterpret_cast<__nv_bfloat162*>(&u));
}
// ---- packed f32x2 helpers (Blackwell) ----
__device__ __forceinline__ ull_t pack2(float lo, float hi) {
    ull_t r; asm("mov.b64 %0, {%1, %2};" : "=l"(r) : "f"(lo), "f"(hi)); return r;
}
__device__ __forceinline__ float2 unpk(ull_t v) {
    float2 f; asm("mov.b64 {%0, %1}, %2;" : "=f"(f.x), "=f"(f.y) : "l"(v)); return f;
}
__device__ __forceinline__ void fma2(ull_t& d, ull_t a, ull_t b) {
    asm("fma.rn.f32x2 %0, %1, %2, %0;" : "+l"(d) : "l"(a), "l"(b));
}
__device__ __forceinline__ float bf_lo(unsigned int u) { return __uint_as_float(u << 16); }
__device__ __forceinline__ float bf_hi(unsigned int u) { return __uint_as_float(u & 0xFFFF0000u); }

// ------------------------- weight prep (permute + transpose + bf16) -------------------------
__global__ void prep_weights(const float* __restrict__ eWhh,
                             const float* __restrict__ dWhh,
                             const float* __restrict__ dWih,
                             const float* __restrict__ dbih,
                             const float* __restrict__ dbhh,
                             const float* __restrict__ dW1) {
    int i = blockIdx.x * 256 + threadIdx.x;
    if (i < 32768) {
        int k = i >> 8, g2 = i & 255;
        int gp0 = 2 * g2, gp1 = 2 * g2 + 1;
        int o0 = (gp0 & 3) * HH + (gp0 >> 2);
        int o1 = (gp1 & 3) * HH + (gp1 >> 2);
        g_WhhB[0][k * 256 + g2] = pack_bf16x2(eWhh[o0 * HH + k], eWhh[o1 * HH + k]);
        g_WhhB[1][k * 256 + g2] = pack_bf16x2(dWhh[o0 * HH + k], dWhh[o1 * HH + k]);
    } else if (i < 33280) {
        int gp = i - 32768;
        int orig = (gp & 3) * HH + (gp >> 2);
        g_dWihP[gp] = dWih[orig];
        g_dbP[gp] = dbih[orig] + dbhh[orig];
    } else if (i < 33280 + 16384) {
        int j = i - 33280;
        int e = j & 127, k2 = j >> 7;   // k2 0..127 covers k 0..255 (W1h then W1c)
        g_W1hcB[k2 * 128 + e] = pack_bf16x2(dW1[e * 384 + 2 * k2],
                                            dW1[e * 384 + 2 * k2 + 1]);
    }
}

// ------------------------- encoder attention (time- & state-invariant) -------------------------
__global__ void prep_attn(const float* __restrict__ x,
                          const float* __restrict__ attnW,
                          const float* __restrict__ attnB) {
    __shared__ float s_s[64];
    __shared__ float red[2];
    int b = blockIdx.x, n = threadIdx.x;
    float s = -1e30f;
    if (n < NINx) {
        float acc = attnB[0];
        const float* wt = attnW + 2 * HH;
        #pragma unroll 8
        for (int t = 0; t < TT; t++) acc = fmaf(x[b * 4096 + t * 64 + n + 1], wt[t], acc);
        s = acc;
    }
    s_s[n] = s;
    __syncthreads();
    if (n < 32) {
        float m = fmaxf(s_s[n], s_s[n + 32]);
        #pragma unroll
        for (int o = 16; o; o >>= 1) m = fmaxf(m, __shfl_xor_sync(0xffffffffu, m, o));
        if (n == 0) red[0] = m;
    }
    __syncthreads();
    float e = (n < NINx) ? expf(s - red[0]) : 0.f;
    s_s[n] = e;
    __syncthreads();
    if (n < 32) {
        float sm = s_s[n] + s_s[n + 32];
        #pragma unroll
        for (int o = 16; o; o >>= 1) sm += __shfl_xor_sync(0xffffffffu, sm, o);
        if (n == 0) red[1] = sm;
    }
    __syncthreads();
    if (n < 64) g_attn[b * 64 + n] = (n < NINx) ? e / red[1] : 0.f;
}

// ------------- gin[b,t,g'] = sum_n attn[b,n]*x[b,t,n+1]*Wih[orig(g'),n] + bias -------------
__global__ __launch_bounds__(256) void gin_gemm(const float* __restrict__ x,
                                                const float* __restrict__ Wih,
                                                const float* __restrict__ bih,
                                                const float* __restrict__ bhh) {
    __shared__ float attn_s[64];
    __shared__ float As[64][68];
    __shared__ float Ws[64][68];
    int bb = blockIdx.x;
    int g0 = blockIdx.y * 64;
    int tid = threadIdx.x;
    if (tid < 64) attn_s[tid] = g_attn[bb * 64 + tid];
    __syncthreads();
    #pragma unroll
    for (int i = 0; i < 16; i++) {
        int idx = tid + i * 256;
        int m = idx >> 6, k = idx & 63;
        As[k][m] = (k < NINx) ? attn_s[k] * x[bb * 4096 + m * 64 + k + 1] : 0.f;
        int gp = g0 + m;
        int orig = (gp & 3) * HH + (gp >> 2);
        Ws[k][m] = (k < NINx) ? Wih[orig * NINx + k] : 0.f;
    }
    __syncthreads();
    int tx = tid & 15, ty = tid >> 4;
    ull_t acc2[4][2];
    #pragma unroll
    for (int i = 0; i < 4; i++) { acc2[i][0] = 0; acc2[i][1] = 0; }
    #pragma unroll 4
    for (int k = 0; k < 64; k++) {
        float4 a = *reinterpret_cast<const float4*>(&As[k][ty * 4]);
        ull_t w01 = *reinterpret_cast<const ull_t*>(&Ws[k][tx * 4]);
        ull_t w23 = *reinterpret_cast<const ull_t*>(&Ws[k][tx * 4 + 2]);
        ull_t a0 = pack2(a.x, a.x), a1 = pack2(a.y, a.y);
        ull_t a2 = pack2(a.z, a.z), a3 = pack2(a.w, a.w);
        fma2(acc2[0][0], a0, w01); fma2(acc2[0][1], a0, w23);
        fma2(acc2[1][0], a1, w01); fma2(acc2[1][1], a1, w23);
        fma2(acc2[2][0], a2, w01); fma2(acc2[2][1], a2, w23);
        fma2(acc2[3][0], a3, w01); fma2(acc2[3][1], a3, w23);
    }
    #pragma unroll
    for (int i = 0; i < 4; i++) {
        int t = ty * 4 + i;
        float2 j01 = unpk(acc2[i][0]), j23 = unpk(acc2[i][1]);
        float accv[4] = {j01.x, j01.y, j23.x, j23.y};
        #pragma unroll
        for (int j = 0; j < 4; j++) {
            int gp = g0 + tx * 4 + j;
            int orig = (gp & 3) * HH + (gp >> 2);
            g_gin[((size_t)bb * TT + t) * 512 + gp] = accv[j] + bih[orig] + bhh[orig];
        }
    }
}

// ------------------------- persistent encoder: 128 blocks x 4 batches, 64 steps -------------------------
struct EncSmem {
    unsigned int whh[128][256];   // bf16x2 [k][g/2]   128 KB
    float hT[128][4];             // [unit][batch]
    float part[3][16][128];       // partials from kq=1..3
};

__global__ __launch_bounds__(512) void enc_persist() {
    extern __shared__ __align__(16) char enc_smem_raw[];
    EncSmem& S = *reinterpret_cast<EncSmem*>(enc_smem_raw);
    int b0 = blockIdx.x * 4;
    int tid = threadIdx.x;
    int ug = tid & 127, kq = tid >> 7;
    {
        const uint4* src = reinterpret_cast<const uint4*>(g_WhhB[0]);
        uint4* dst = reinterpret_cast<uint4*>(&S.whh[0][0]);
        for (int i = tid; i < 8192; i += 512) dst[i] = src[i];
    }
    if (tid < 128) *reinterpret_cast<float4*>(S.hT[tid]) = make_float4(0.f, 0.f, 0.f, 0.f);
    float c0 = 0.f, c1 = 0.f, c2 = 0.f, c3 = 0.f;
    __syncthreads();
    for (int t = 0; t < 64; t++) {
        float4 gin0, gin1, gin2, gin3;
        if (kq == 0) {
            const float* gp = g_gin + ((size_t)b0 * 64 + t) * 512 + ug * 4;
            gin0 = *reinterpret_cast<const float4*>(gp);
            gin1 = *reinterpret_cast<const float4*>(gp + 32768);
            gin2 = *reinterpret_cast<const float4*>(gp + 65536);
            gin3 = *reinterpret_cast<const float4*>(gp + 98304);
        }
        ull_t a01[4] = {0, 0, 0, 0}, a23[4] = {0, 0, 0, 0};
        #pragma unroll 8
        for (int j = 0; j < 32; j++) {
            int k = kq * 32 + j;
            uint2 wp = *reinterpret_cast<const uint2*>(&S.whh[k][ug * 2]);
            ull_t h01 = *reinterpret_cast<const ull_t*>(&S.hT[k][0]);
            ull_t h23 = *reinterpret_cast<const ull_t*>(&S.hT[k][2]);
            ull_t d0 = pack2(bf_lo(wp.x), bf_lo(wp.x));
            ull_t d1 = pack2(bf_hi(wp.x), bf_hi(wp.x));
            ull_t d2 = pack2(bf_lo(wp.y), bf_lo(wp.y));
            ull_t d3 = pack2(bf_hi(wp.y), bf_hi(wp.y));
            fma2(a01[0], d0, h01); fma2(a23[0], d0, h23);
            fma2(a01[1], d1, h01); fma2(a23[1], d1, h23);
            fma2(a01[2], d2, h01); fma2(a23[2], d2, h23);
            fma2(a01[3], d3, h01); fma2(a23[3], d3, h23);
        }
        float a[16];
        #pragma unroll
        for (int j = 0; j < 4; j++) {
            float2 f01 = unpk(a01[j]), f23 = unpk(a23[j]);
            a[j] = f01.x; a[4 + j] = f01.y; a[8 + j] = f23.x; a[12 + j] = f23.y;
        }
        if (kq) {
            #pragma unroll
            for (int j = 0; j < 16; j++) S.part[kq - 1][j][ug] = a[j];
        }
        __syncthreads();
        if (kq == 0) {
            #pragma unroll
            for (int j = 0; j < 16; j++)
                a[j] += S.part[0][j][ug] + S.part[1][j][ug] + S.part[2][j][ug];
            float nh0, nh1, nh2, nh3;
            {
                float gi = a[0] + gin0.x, gf = a[1] + gin0.y, gg = a[2] + gin0.z, go = a[3] + gin0.w;
                float cv = sig_fast(gf) * c0 + sig_fast(gi) * tanh_fast(gg);
                c0 = cv; nh0 = sig_fast(go) * tanh_fast(cv);
            }
            {
                float gi = a[4] + gin1.x, gf = a[5] + gin1.y, gg = a[6] + gin1.z, go = a[7] + gin1.w;
                float cv = sig_fast(gf) * c1 + sig_fast(gi) * tanh_fast(gg);
                c1 = cv; nh1 = sig_fast(go) * tanh_fast(cv);
            }
            {
                float gi = a[8] + gin2.x, gf = a[9] + gin2.y, gg = a[10] + gin2.z, go = a[11] + gin2.w;
                float cv = sig_fast(gf) * c2 + sig_fast(gi) * tanh_fast(gg);
                c2 = cv; nh2 = sig_fast(go) * tanh_fast(cv);
            }
            {
                float gi = a[12] + gin3.x, gf = a[13] + gin3.y, gg = a[14] + gin3.z, go = a[15] + gin3.w;
                float cv = sig_fast(gf) * c3 + sig_fast(gi) * tanh_fast(gg);
                c3 = cv; nh3 = sig_fast(go) * tanh_fast(cv);
            }
            *reinterpret_cast<float4*>(S.hT[ug]) = make_float4(nh0, nh1, nh2, nh3);
            g_enc[((size_t)(b0 + 0) * TT + t) * HH + ug] = nh0;
            g_enc[((size_t)(b0 + 1) * TT + t) * HH + ug] = nh1;
            g_enc[((size_t)(b0 + 2) * TT + t) * HH + ug] = nh2;
            g_enc[((size_t)(b0 + 3) * TT + t) * HH + ug] = nh3;
        }
        __syncthreads();
    }
}

// ------------------ enc_proj = input_encoded @ W1e^T + dec_b1 (fp32, f32x2 math) ------------------
__global__ __launch_bounds__(256) void eproj_gemm(const float* __restrict__ W1,
                                                  const float* __restrict__ b1) {
    __shared__ float As[64][68];
    __shared__ float Ws[64][68];
    int m0 = blockIdx.x * 64;
    int n0 = blockIdx.y * 64;
    int tid = threadIdx.x;
    int tx = tid & 15, ty = tid >> 4;
    ull_t acc2[4][2];
    #pragma unroll
    for (int i = 0; i < 4; i++) { acc2[i][0] = 0; acc2[i][1] = 0; }
    for (int kc = 0; kc < 2; kc++) {
        __syncthreads();
        #pragma unroll
        for (int i = 0; i < 16; i++) {
            int idx = tid + i * 256;
            int m = idx >> 6, k = idx & 63;
            As[k][m] = g_enc[(size_t)(m0 + m) * HH + kc * 64 + k];
            Ws[k][m] = W1[(n0 + m) * 384 + 256 + kc * 64 + k];
        }
        __syncthreads();
        #pragma unroll 4
        for (int k = 0; k < 64; k++) {
            float4 a = *reinterpret_cast<const float4*>(&As[k][ty * 4]);
            ull_t w01 = *reinterpret_cast<const ull_t*>(&Ws[k][tx * 4]);
            ull_t w23 = *reinterpret_cast<const ull_t*>(&Ws[k][tx * 4 + 2]);
            ull_t a0 = pack2(a.x, a.x), a1 = pack2(a.y, a.y);
            ull_t a2 = pack2(a.z, a.z), a3 = pack2(a.w, a.w);
            fma2(acc2[0][0], a0, w01); fma2(acc2[0][1], a0, w23);
            fma2(acc2[1][0], a1, w01); fma2(acc2[1][1], a1, w23);
            fma2(acc2[2][0], a2, w01); fma2(acc2[2][1], a2, w23);
            fma2(acc2[3][0], a3, w01); fma2(acc2[3][1], a3, w23);
        }
    }
    #pragma unroll
    for (int i = 0; i < 4; i++) {
        int row = m0 + ty * 4 + i;
        float2 j01 = unpk(acc2[i][0]), j23 = unpk(acc2[i][1]);
        float accv[4] = {j01.x, j01.y, j23.x, j23.y};
        #pragma unroll
        for (int j = 0; j < 4; j++) {
            int n = n0 + tx * 4 + j;
            g_eproj[(size_t)row * HH + n] = accv[j] + b1[n];
        }
    }
}

// ------------------------- persistent decoder: 128 blocks x 4 batches, 64 steps -------------------------
// 512 threads. whh (bf16, 128K) + enc (bf16, 64K) smem-resident.
// Phase G split: warps 0-7 gates GEMM (k-halves), warps 8-15 u GEMM (h-half / c-half).
struct DecSmem {
    unsigned int whh[128][256];   // 128 KB
    unsigned int encB[4][64][64]; // 64 KB  [bb][tt][e/2] bf16x2
    float hcT[256][4];            // 4 KB: rows 0..127 h, 128..255 c
    float partC[16][128];         // 8 KB  gates partials (kh=1)
    float4 partU[128];            // 2 KB  u partials (uh=1)
    float u_s[4][128];
    float ctx_s[4][128];
    float sc[4][64];
    float W2_s[128];
    float fcW_s[128];
    float redy[4][2];
    float xh[4][64];
};

__global__ __launch_bounds__(512) void dec_persist(const float* __restrict__ x,
                                                   const float* __restrict__ dW2,
                                                   const float* __restrict__ fcW,
                                                   const float* __restrict__ fcb,
                                                   const float* __restrict__ fcfW,
                                                   const float* __restrict__ fcfb,
                                                   float* __restrict__ out) {
    extern __shared__ __align__(16) char dec_smem_raw[];
    DecSmem& S = *reinterpret_cast<DecSmem*>(dec_smem_raw);
    int b0 = blockIdx.x * 4;
    int tid = threadIdx.x, lane = tid & 31, wid = tid >> 5;
    int ug = tid & 127;
    float4 wv = make_float4(0.f, 0.f, 0.f, 0.f), bv = wv;
    if (tid < 128) {
        wv = *reinterpret_cast<const float4*>(&g_dWihP[ug * 4]);
        bv = *reinterpret_cast<const float4*>(&g_dbP[ug * 4]);
    }
    // ---- prologue ----
    {
        const uint4* src = reinterpret_cast<const uint4*>(g_WhhB[1]);
        uint4* dst = reinterpret_cast<uint4*>(&S.whh[0][0]);
        for (int i = tid; i < 8192; i += 512) dst[i] = src[i];
    }
    for (int idx = tid; idx < 4 * 64 * 64; idx += 512) {
        int bb = idx >> 12, r = idx & 4095;
        int tt = r >> 6, e2 = r & 63;
        const float* src = g_enc + ((size_t)(b0 + bb) * TT + tt) * HH + 2 * e2;
        S.encB[bb][tt][e2] = pack_bf16x2(src[0], src[1]);
    }
    if (tid < 256) {
        *reinterpret_cast<float4*>(S.hcT[tid]) = make_float4(0.f, 0.f, 0.f, 0.f);
        int bb = tid >> 6, tt = tid & 63;
        S.xh[bb][tt] = x[(size_t)(b0 + bb) * 4096 + tt * 64];
    }
    if (tid < 128) { S.W2_s[tid] = dW2[tid]; S.fcW_s[tid] = fcW[tid]; }
    float fcW128 = fcW[128], fcb0 = fcb[0];
    __syncthreads();

    for (int t = 0; t < 64; t++) {
        // ===== phase G: warps 0-7 gates GEMM, warps 8-15 u GEMM =====
        float a[16];
        ull_t u01 = 0, u23 = 0;
        if (tid < 256) {
            int kh = tid >> 7;   // k-half
            ull_t a01[4] = {0, 0, 0, 0}, a23[4] = {0, 0, 0, 0};
            #pragma unroll 8
            for (int j = 0; j < 64; j++) {
                int k = kh * 64 + j;
                uint2 wp = *reinterpret_cast<const uint2*>(&S.whh[k][ug * 2]);
                ull_t h01 = *reinterpret_cast<const ull_t*>(&S.hcT[k][0]);
                ull_t h23 = *reinterpret_cast<const ull_t*>(&S.hcT[k][2]);
                ull_t d0 = pack2(bf_lo(wp.x), bf_lo(wp.x));
                ull_t d1 = pack2(bf_hi(wp.x), bf_hi(wp.x));
                ull_t d2 = pack2(bf_lo(wp.y), bf_lo(wp.y));
                ull_t d3 = pack2(bf_hi(wp.y), bf_hi(wp.y));
                fma2(a01[0], d0, h01); fma2(a23[0], d0, h23);
                fma2(a01[1], d1, h01); fma2(a23[1], d1, h23);
                fma2(a01[2], d2, h01); fma2(a23[2], d2, h23);
                fma2(a01[3], d3, h01); fma2(a23[3], d3, h23);
            }
            #pragma unroll
            for (int j = 0; j < 4; j++) {
                float2 f01 = unpk(a01[j]), f23 = unpk(a23[j]);
                a[j] = f01.x; a[4 + j] = f01.y; a[8 + j] = f23.x; a[12 + j] = f23.y;
            }
            if (kh) {
                #pragma unroll
                for (int j = 0; j < 16; j++) S.partC[j][ug] = a[j];
            }
        } else {
            int uh = (tid >> 7) & 1;  // 0: W1h over h, 1: W1c over c
            #pragma unroll 8
            for (int j2 = 0; j2 < 64; j2++) {
                int k2 = uh * 64 + j2;
                unsigned int wp = g_W1hcB[k2 * 128 + ug];
                ull_t h0_01 = *reinterpret_cast<const ull_t*>(&S.hcT[2 * k2][0]);
                ull_t h0_23 = *reinterpret_cast<const ull_t*>(&S.hcT[2 * k2][2]);
                ull_t h1_01 = *reinterpret_cast<const ull_t*>(&S.hcT[2 * k2 + 1][0]);
                ull_t h1_23 = *reinterpret_cast<const ull_t*>(&S.hcT[2 * k2 + 1][2]);
                ull_t d0 = pack2(bf_lo(wp), bf_lo(wp));
                ull_t d1 = pack2(bf_hi(wp), bf_hi(wp));
                fma2(u01, d0, h0_01); fma2(u23, d0, h0_23);
                fma2(u01, d1, h1_01); fma2(u23, d1, h1_23);
            }
            if (uh) {
                float2 f0 = unpk(u01), f2 = unpk(u23);
                S.partU[ug] = make_float4(f0.x, f0.y, f2.x, f2.y);
            }
        }
        __syncthreads();
        // combine: tid<128 gates into regs; warps 8-11 combine u into u_s
        if (tid < 128) {
            #pragma unroll
            for (int j = 0; j < 16; j++) a[j] += S.partC[j][ug];
        } else if ((tid >> 7) == 2) {
            float2 f0 = unpk(u01), f2 = unpk(u23);
            float4 p = S.partU[ug];
            S.u_s[0][ug] = f0.x + p.x;
            S.u_s[1][ug] = f0.y + p.y;
            S.u_s[2][ug] = f2.x + p.z;
            S.u_s[3][ug] = f2.y + p.w;
        }
        __syncthreads();
        // ===== phase B1: scores (warp per (batch,t'); eproj fp32 from L2, MLP 8) =====
        #pragma unroll 8
        for (int it = 0; it < 16; it++) {
            int task = it * 16 + wid;
            int bb = task >> 6, tt = task & 63;
            float4 e4 = *reinterpret_cast<const float4*>(
                g_eproj + ((size_t)(b0 + bb) * TT + tt) * HH + lane * 4);
            float4 u4 = *reinterpret_cast<const float4*>(&S.u_s[bb][lane * 4]);
            float4 w4 = *reinterpret_cast<const float4*>(&S.W2_s[lane * 4]);
            float p = w4.x * tanh_fast(e4.x + u4.x) + w4.y * tanh_fast(e4.y + u4.y)
                    + w4.z * tanh_fast(e4.z + u4.z) + w4.w * tanh_fast(e4.w + u4.w);
            #pragma unroll
            for (int o = 16; o; o >>= 1) p += __shfl_xor_sync(0xffffffffu, p, o);
            if (lane == 0) S.sc[bb][tt] = p;
        }
        __syncthreads();
        // ===== phase B2: softmax (warps 4-7, one per batch) =====
        if (wid >= 4 && wid < 8) {
            int bb = wid - 4;
            float s0 = S.sc[bb][lane], s1 = S.sc[bb][lane + 32];
            float m = fmaxf(s0, s1);
            #pragma unroll
            for (int o = 16; o; o >>= 1) m = fmaxf(m, __shfl_xor_sync(0xffffffffu, m, o));
            float e0 = __expf(s0 - m), e1 = __expf(s1 - m);
            float sm = e0 + e1;
            #pragma unroll
            for (int o = 16; o; o >>= 1) sm += __shfl_xor_sync(0xffffffffu, sm, o);
            float inv = 1.0f / sm;
            S.sc[bb][lane] = e0 * inv;
            S.sc[bb][lane + 32] = e1 * inv;
        }
        __syncthreads();
        // ===== phase B3: context + y partials (tid<256; enc bf16 from SMEM) =====
        if (tid < 256) {
            int bb = tid >> 6, e2 = tid & 63;
            float cx0 = 0.f, cx1 = 0.f;
            #pragma unroll 8
            for (int tt = 0; tt < 64; tt++) {
                float2 f = unpack_bf16x2(S.encB[bb][tt][e2]);
                float av = S.sc[bb][tt];
                cx0 = fmaf(av, f.x, cx0);
                cx1 = fmaf(av, f.y, cx1);
            }
            S.ctx_s[bb][2 * e2] = cx0;
            S.ctx_s[bb][2 * e2 + 1] = cx1;
            float p = cx0 * S.fcW_s[2 * e2] + cx1 * S.fcW_s[2 * e2 + 1];
            #pragma unroll
            for (int o = 16; o; o >>= 1) p += __shfl_xor_sync(0xffffffffu, p, o);
            if (lane == 0) S.redy[bb][(tid >> 5) & 1] = p;
        }
        __syncthreads();
        // ===== epilogue: LSTM cells (tid<128; a[16] in registers) =====
        if (tid < 128) {
            float yv[4];
            #pragma unroll
            for (int b = 0; b < 4; b++)
                yv[b] = S.redy[b][0] + S.redy[b][1] + S.xh[b][t] * fcW128 + fcb0;
            float4 co = *reinterpret_cast<const float4*>(S.hcT[128 + ug]);
            float cvals[4] = {co.x, co.y, co.z, co.w};
            float nh[4], nc[4];
            #pragma unroll
            for (int b = 0; b < 4; b++) {
                float y = yv[b];
                float gi = a[b * 4 + 0] + y * wv.x + bv.x;
                float gf = a[b * 4 + 1] + y * wv.y + bv.y;
                float gg = a[b * 4 + 2] + y * wv.z + bv.z;
                float go = a[b * 4 + 3] + y * wv.w + bv.w;
                float cv = sig_fast(gf) * cvals[b] + sig_fast(gi) * tanh_fast(gg);
                nc[b] = cv;
                nh[b] = sig_fast(go) * tanh_fast(cv);
            }
            *reinterpret_cast<float4*>(S.hcT[128 + ug]) = make_float4(nc[0], nc[1], nc[2], nc[3]);
            *reinterpret_cast<float4*>(S.hcT[ug]) = make_float4(nh[0], nh[1], nh[2], nh[3]);
        }
        __syncthreads();
    }

    // ---- final: out[b] = [h, ctx] @ fcf_W^T + fcf_b ----
    if (tid < 128) {
        int bb = wid;  // 0..3
        float p = 0.f;
        #pragma unroll
        for (int q = 0; q < 4; q++) {
            int e = lane + 32 * q;
            p += S.hcT[e][bb] * fcfW[e] + S.ctx_s[bb][e] * fcfW[128 + e];
        }
        #pragma unroll
        for (int o = 16; o; o >>= 1) p += __shfl_xor_sync(0xffffffffu, p, o);
        if (lane == 0) out[b0 + bb] = p + fcfb[0];
    }
}

// ------------------------- launch -------------------------
extern "C" void kernel_launch(void* const* d_in, const int* in_sizes, int n_in,
                              void* d_out, int out_size) {
    const float* x        = (const float*)d_in[0];
    const float* attnW    = (const float*)d_in[1];
    const float* attnB    = (const float*)d_in[2];
    const float* enc_Wih  = (const float*)d_in[3];
    const float* enc_Whh  = (const float*)d_in[4];
    const float* enc_bih  = (const float*)d_in[5];
    const float* enc_bhh  = (const float*)d_in[6];
    const float* dec_W1   = (const float*)d_in[7];
    const float* dec_b1   = (const float*)d_in[8];
    const float* dec_W2   = (const float*)d_in[9];
    // d_in[10] = dec_b2 (cancels in softmax)
    const float* dec_Wih  = (const float*)d_in[11];
    const float* dec_Whh  = (const float*)d_in[12];
    const float* dec_bih  = (const float*)d_in[13];
    const float* dec_bhh  = (const float*)d_in[14];
    const float* fc_W     = (const float*)d_in[15];
    const float* fc_b     = (const float*)d_in[16];
    const float* fcf_W    = (const float*)d_in[17];
    const float* fcf_b    = (const float*)d_in[18];
    float* out = (float*)d_out;

    int enc_smem = (int)sizeof(EncSmem);
    int dec_smem = (int)sizeof(DecSmem);
    cudaFuncSetAttribute(enc_persist, cudaFuncAttributeMaxDynamicSharedMemorySize, enc_smem);
    cudaFuncSetAttribute(dec_persist, cudaFuncAttributeMaxDynamicSharedMemorySize, dec_smem);

    prep_weights<<<195, 256>>>(enc_Whh, dec_Whh, dec_Wih, dec_bih, dec_bhh, dec_W1);
    prep_attn<<<BB, 64>>>(x, attnW, attnB);
    gin_gemm<<<dim3(BB, 8), 256>>>(x, enc_Wih, enc_bih, enc_bhh);
    enc_persist<<<128, 512, enc_smem>>>();
    eproj_gemm<<<dim3(512, 2), 256>>>(dec_W1, dec_b1);
    dec_persist<<<128, 512, dec_smem>>>(x, dec_W2, fc_W, fc_b, fcf_W, fcf_b, out);
}